// round 1
// baseline (speedup 1.0000x reference)
#include <cuda_runtime.h>
#include <cuda_bf16.h>
#include <math.h>

// ---------------------------------------------------------------------------
// Problem constants
// ---------------------------------------------------------------------------
#define BB   2
#define SS   2048
#define DD   2048
#define HH   16
#define DHH  128
#define FFN  5632
#define ROWS (BB*SS)           // 4096
#define NQKV (3*HH*DHH)        // 6144
#define NFC  (2*FFN)           // 11264

// ---------------------------------------------------------------------------
// Scratch (static device globals; allocation is forbidden)
// ---------------------------------------------------------------------------
__device__ float g_X  [ROWS*DD];     // LN1 out
__device__ float g_QKV[ROWS*NQKV];   // qkv proj
__device__ float g_Q  [ROWS*DD];     // [B,H,S,DH]
__device__ float g_K  [ROWS*DD];
__device__ float g_V  [ROWS*DD];
__device__ float g_CTX[ROWS*DD];     // [B,S,H*DH]
__device__ float g_H1 [ROWS*DD];     // residual 1
__device__ float g_X2 [ROWS*DD];     // LN2 out
__device__ float g_AB [ROWS*NFC];    // fc_in out
__device__ float g_G  [ROWS*FFN];    // swiglu out

// ---------------------------------------------------------------------------
// LayerNorm: one block per row (2048 cols), 256 threads, 8 elems/thread
// ---------------------------------------------------------------------------
__global__ void __launch_bounds__(256) ln_kernel(
    const float* __restrict__ X, const float* __restrict__ g,
    const float* __restrict__ b, float* __restrict__ Y)
{
    const int tid = threadIdx.x;
    const float* x = X + (size_t)blockIdx.x * DD;
    float* y = Y + (size_t)blockIdx.x * DD;

    float v[8];
    *(float4*)&v[0] = *(const float4*)&x[tid*8];
    *(float4*)&v[4] = *(const float4*)&x[tid*8 + 4];

    float s = 0.f, sq = 0.f;
#pragma unroll
    for (int i = 0; i < 8; i++) { s += v[i]; sq += v[i]*v[i]; }
#pragma unroll
    for (int o = 16; o; o >>= 1) {
        s  += __shfl_xor_sync(0xffffffffu, s,  o);
        sq += __shfl_xor_sync(0xffffffffu, sq, o);
    }
    __shared__ float red[2][8];
    __shared__ float stats[2];
    const int w = tid >> 5, l = tid & 31;
    if (l == 0) { red[0][w] = s; red[1][w] = sq; }
    __syncthreads();
    if (tid == 0) {
        float S = 0.f, SQ = 0.f;
#pragma unroll
        for (int i = 0; i < 8; i++) { S += red[0][i]; SQ += red[1][i]; }
        const float mean = S * (1.0f/DD);
        const float var  = SQ * (1.0f/DD) - mean*mean;
        stats[0] = mean;
        stats[1] = rsqrtf(var + 1e-5f);
    }
    __syncthreads();
    const float mean = stats[0], rstd = stats[1];

    float gv[8], bv[8];
    *(float4*)&gv[0] = *(const float4*)&g[tid*8];
    *(float4*)&gv[4] = *(const float4*)&g[tid*8+4];
    *(float4*)&bv[0] = *(const float4*)&b[tid*8];
    *(float4*)&bv[4] = *(const float4*)&b[tid*8+4];
#pragma unroll
    for (int i = 0; i < 8; i++) v[i] = (v[i] - mean) * rstd * gv[i] + bv[i];
    *(float4*)&y[tid*8]     = *(float4*)&v[0];
    *(float4*)&y[tid*8 + 4] = *(float4*)&v[4];
}

// ---------------------------------------------------------------------------
// SGEMM: C[M,N] = A[M,K] @ B[K,N] (+R). 128x128x16 tile, 8x8 microtile.
// All dims divisible by 128/16 for this problem -> no bounds checks.
// ---------------------------------------------------------------------------
template<int EPI>
__global__ void __launch_bounds__(256, 2) sgemm_kernel(
    const float* __restrict__ A, const float* __restrict__ Bm,
    const float* __restrict__ R, float* __restrict__ C,
    int M, int N, int K)
{
    __shared__ float As[16][132];   // transposed A tile, padded
    __shared__ float Bs[16][128];

    const int tid = threadIdx.x;
    const int tx = tid & 15, ty = tid >> 4;
    const int bx = blockIdx.x, by = blockIdx.y;

    const float* Ab = A  + (size_t)(by * 128) * K;
    const float* Bb = Bm + (size_t)(bx * 128);

    float acc[8][8];
#pragma unroll
    for (int i = 0; i < 8; i++)
#pragma unroll
        for (int j = 0; j < 8; j++) acc[i][j] = 0.f;

    for (int kt = 0; kt < K; kt += 16) {
#pragma unroll
        for (int l = 0; l < 2; l++) {
            const int f  = tid + l * 256;
            const int r  = f >> 2;
            const int c4 = (f & 3) << 2;
            float4 v = *(const float4*)&Ab[(size_t)r * K + kt + c4];
            As[c4+0][r] = v.x; As[c4+1][r] = v.y;
            As[c4+2][r] = v.z; As[c4+3][r] = v.w;
        }
#pragma unroll
        for (int l = 0; l < 2; l++) {
            const int f = tid + l * 256;
            const int r = f >> 5;
            const int c = (f & 31) << 2;
            *(float4*)&Bs[r][c] = *(const float4*)&Bb[(size_t)(kt + r) * N + c];
        }
        __syncthreads();
#pragma unroll
        for (int k = 0; k < 16; k++) {
            float a[8], bb[8];
            *(float4*)&a[0]  = *(float4*)&As[k][ty*8];
            *(float4*)&a[4]  = *(float4*)&As[k][ty*8 + 4];
            *(float4*)&bb[0] = *(float4*)&Bs[k][tx*8];
            *(float4*)&bb[4] = *(float4*)&Bs[k][tx*8 + 4];
#pragma unroll
            for (int i = 0; i < 8; i++)
#pragma unroll
                for (int j = 0; j < 8; j++) acc[i][j] += a[i] * bb[j];
        }
        __syncthreads();
    }

    const int row0 = by * 128 + ty * 8;
    const int col0 = bx * 128 + tx * 8;
#pragma unroll
    for (int i = 0; i < 8; i++) {
        const size_t off = (size_t)(row0 + i) * N + col0;
        float4 c0 = *(float4*)&acc[i][0];
        float4 c1 = *(float4*)&acc[i][4];
        if (EPI == 1) {
            float4 r0 = *(const float4*)&R[off];
            float4 r1 = *(const float4*)&R[off + 4];
            c0.x += r0.x; c0.y += r0.y; c0.z += r0.z; c0.w += r0.w;
            c1.x += r1.x; c1.y += r1.y; c1.z += r1.z; c1.w += r1.w;
        }
        *(float4*)&C[off]     = c0;
        *(float4*)&C[off + 4] = c1;
    }
}

// ---------------------------------------------------------------------------
// RoPE + scatter: QKV[B,S,H,3*DH] -> Q/K/V [B,H,S,DH] (rope on Q,K)
// grid (B*S, H), 128 threads
// ---------------------------------------------------------------------------
__global__ void __launch_bounds__(128) rope_kernel(
    const float* __restrict__ QKV, const int* __restrict__ pos_ids,
    float* __restrict__ Q, float* __restrict__ K, float* __restrict__ V)
{
    const int bs = blockIdx.x;       // 0..4095
    const int h  = blockIdx.y;       // 0..15
    const int d  = threadIdx.x;      // 0..127
    const int pos = pos_ids[bs];

    const float* row = QKV + (size_t)bs * NQKV + h * (3*DHH);
    const float q = row[d];
    const float k = row[DHH + d];
    const float v = row[2*DHH + d];

    const int j = d & 63;
    const float inv = 1.0f / powf(10000.0f, (float)(2*j) * (1.0f/128.0f));
    const float fr = (float)pos * inv;
    const float sn = sinf(fr), cs = cosf(fr);

    float qo, ko;
    if (d < 64) {
        qo = q * cs - row[d + 64] * sn;
        ko = k * cs - row[DHH + d + 64] * sn;
    } else {
        qo = q * cs + row[d - 64] * sn;
        ko = k * cs + row[DHH + d - 64] * sn;
    }
    const int b = bs >> 11, s = bs & 2047;
    const size_t o = (((size_t)(b*HH + h)) * SS + s) * DHH + d;
    Q[o] = qo; K[o] = ko; V[o] = v;
}

// ---------------------------------------------------------------------------
// Flash attention (fp32): 64 q-rows per block, 64-col K/V tiles, online softmax.
// 256 threads: thread (tx,ty) owns score microtile 4x4 and output 4 rows x 8 cols.
// ---------------------------------------------------------------------------
#define ATT_SMEM_FLOATS (128*68 + 128*68 + 64*128 + 64*68)
#define ATT_SMEM_BYTES  (ATT_SMEM_FLOATS * 4)

__global__ void __launch_bounds__(256) attn_kernel(
    const float* __restrict__ Q, const float* __restrict__ K,
    const float* __restrict__ V, const unsigned char* __restrict__ mask,
    float* __restrict__ CTX)
{
    extern __shared__ float sm[];
    float* Qs = sm;                  // [128][68] k-major (transposed)
    float* Ks = Qs + 128*68;         // [128][68] k-major
    float* Vs = Ks + 128*68;         // [64][128] row-major
    float* Ps = Vs + 64*128;         // [64][68]

    const int tid = threadIdx.x;
    const int tx = tid & 15, ty = tid >> 4;
    const int qt = blockIdx.x, h = blockIdx.y, b = blockIdx.z;

    const size_t headoff = ((size_t)(b*HH + h)) * SS * DHH;
    const float* Qg = Q + headoff + (size_t)qt * 64 * DHH;

    for (int f = tid; f < 2048; f += 256) {
        const int r = f >> 5;
        const int k = (f & 31) << 2;
        float4 t = *(const float4*)&Qg[r*DHH + k];
        Qs[(k+0)*68 + r] = t.x; Qs[(k+1)*68 + r] = t.y;
        Qs[(k+2)*68 + r] = t.z; Qs[(k+3)*68 + r] = t.w;
    }

    float m_run[4], l_run[4], O[4][8];
#pragma unroll
    for (int i = 0; i < 4; i++) {
        m_run[i] = -1e30f; l_run[i] = 0.f;
#pragma unroll
        for (int c = 0; c < 8; c++) O[i][c] = 0.f;
    }
    const float scale = 0.08838834764831845f;  // 1/sqrt(128)
    const unsigned char* mrow = mask + (size_t)b * SS * SS;
    const int qbase = qt * 64 + ty * 4;

    for (int kt = 0; kt < SS; kt += 64) {
        __syncthreads();   // previous iteration fully consumed Ks/Vs/Ps
        const float* Kg = K + headoff + (size_t)kt * DHH;
        const float* Vg = V + headoff + (size_t)kt * DHH;
        for (int f = tid; f < 2048; f += 256) {
            const int r = f >> 5;
            const int k = (f & 31) << 2;
            float4 t = *(const float4*)&Kg[r*DHH + k];
            Ks[(k+0)*68 + r] = t.x; Ks[(k+1)*68 + r] = t.y;
            Ks[(k+2)*68 + r] = t.z; Ks[(k+3)*68 + r] = t.w;
            ((float4*)Vs)[f] = *(const float4*)&Vg[r*DHH + k];
        }
        __syncthreads();

        float s[4][4];
#pragma unroll
        for (int i = 0; i < 4; i++)
#pragma unroll
            for (int j = 0; j < 4; j++) s[i][j] = 0.f;

#pragma unroll 4
        for (int k = 0; k < 128; k++) {
            float4 qv = *(float4*)&Qs[k*68 + ty*4];
            float4 kv = *(float4*)&Ks[k*68 + tx*4];
            const float q0[4] = {qv.x, qv.y, qv.z, qv.w};
            const float k0[4] = {kv.x, kv.y, kv.z, kv.w};
#pragma unroll
            for (int i = 0; i < 4; i++)
#pragma unroll
                for (int j = 0; j < 4; j++) s[i][j] += q0[i] * k0[j];
        }

#pragma unroll
        for (int i = 0; i < 4; i++) {
#pragma unroll
            for (int j = 0; j < 4; j++) {
                float sv = s[i][j] * scale;
                if (mrow[(size_t)(qbase + i) * SS + kt + tx*4 + j]) sv = -10000.f;
                s[i][j] = sv;
            }
            float mt = fmaxf(fmaxf(s[i][0], s[i][1]), fmaxf(s[i][2], s[i][3]));
#pragma unroll
            for (int o = 8; o; o >>= 1) mt = fmaxf(mt, __shfl_xor_sync(0xffffffffu, mt, o));
            const float mnew = fmaxf(m_run[i], mt);
            float p[4], sum = 0.f;
#pragma unroll
            for (int j = 0; j < 4; j++) { p[j] = expf(s[i][j] - mnew); sum += p[j]; }
#pragma unroll
            for (int o = 8; o; o >>= 1) sum += __shfl_xor_sync(0xffffffffu, sum, o);
            const float cf = expf(m_run[i] - mnew);
            l_run[i] = l_run[i] * cf + sum;
            m_run[i] = mnew;
#pragma unroll
            for (int c = 0; c < 8; c++) O[i][c] *= cf;
            Ps[(ty*4 + i)*68 + tx*4 + 0] = p[0];
            Ps[(ty*4 + i)*68 + tx*4 + 1] = p[1];
            Ps[(ty*4 + i)*68 + tx*4 + 2] = p[2];
            Ps[(ty*4 + i)*68 + tx*4 + 3] = p[3];
        }
        __syncthreads();

#pragma unroll 2
        for (int jj = 0; jj < 64; jj++) {
            float4 v0 = *(float4*)&Vs[jj*128 + tx*8];
            float4 v1 = *(float4*)&Vs[jj*128 + tx*8 + 4];
            const float vv[8] = {v0.x, v0.y, v0.z, v0.w, v1.x, v1.y, v1.z, v1.w};
#pragma unroll
            for (int i = 0; i < 4; i++) {
                const float p = Ps[(ty*4 + i)*68 + jj];
#pragma unroll
                for (int c = 0; c < 8; c++) O[i][c] += p * vv[c];
            }
        }
    }

    // epilogue: normalize and write ctx [B,S,H*DH]
#pragma unroll
    for (int i = 0; i < 4; i++) {
        const float inv = 1.0f / l_run[i];
        float4 o0 = {O[i][0]*inv, O[i][1]*inv, O[i][2]*inv, O[i][3]*inv};
        float4 o1 = {O[i][4]*inv, O[i][5]*inv, O[i][6]*inv, O[i][7]*inv};
        const size_t off = ((size_t)(b*SS + qbase + i)) * DD + h*DHH + tx*8;
        *(float4*)&CTX[off]     = o0;
        *(float4*)&CTX[off + 4] = o1;
    }
}

// ---------------------------------------------------------------------------
// SwiGLU: g = silu(a) * b, a/b split from AB[rows, 2*FFN]
// ---------------------------------------------------------------------------
__global__ void __launch_bounds__(256) swiglu_kernel(
    const float* __restrict__ AB, float* __restrict__ G)
{
    const int idx = blockIdx.x * blockDim.x + threadIdx.x;   // float4 index
    const int total4 = ROWS * FFN / 4;
    if (idx >= total4) return;
    const int e = idx * 4;
    const int r = e / FFN;
    const int c = e - r * FFN;
    const float* row = AB + (size_t)r * NFC;
    float4 a = *(const float4*)&row[c];
    float4 bb = *(const float4*)&row[FFN + c];
    float4 o;
    o.x = a.x / (1.0f + expf(-a.x)) * bb.x;
    o.y = a.y / (1.0f + expf(-a.y)) * bb.y;
    o.z = a.z / (1.0f + expf(-a.z)) * bb.z;
    o.w = a.w / (1.0f + expf(-a.w)) * bb.w;
    *(float4*)&G[(size_t)r * FFN + c] = o;
}

// ---------------------------------------------------------------------------
// Launch
// ---------------------------------------------------------------------------
extern "C" void kernel_launch(void* const* d_in, const int* in_sizes, int n_in,
                              void* d_out, int out_size)
{
    const float*         hidden  = (const float*)d_in[0];
    const unsigned char* mask    = (const unsigned char*)d_in[1];
    const int*           pos     = (const int*)d_in[2];
    const float*         ln1_g   = (const float*)d_in[3];
    const float*         ln1_b   = (const float*)d_in[4];
    const float*         Wqkv    = (const float*)d_in[5];
    const float*         Wo      = (const float*)d_in[6];
    const float*         ln2_g   = (const float*)d_in[7];
    const float*         ln2_b   = (const float*)d_in[8];
    const float*         Wfc_in  = (const float*)d_in[9];
    const float*         Wfc_out = (const float*)d_in[10];
    float*               out     = (float*)d_out;

    float *X, *QKV, *Q, *K, *V, *CTX, *H1, *X2, *AB, *G;
    cudaGetSymbolAddress((void**)&X,   g_X);
    cudaGetSymbolAddress((void**)&QKV, g_QKV);
    cudaGetSymbolAddress((void**)&Q,   g_Q);
    cudaGetSymbolAddress((void**)&K,   g_K);
    cudaGetSymbolAddress((void**)&V,   g_V);
    cudaGetSymbolAddress((void**)&CTX, g_CTX);
    cudaGetSymbolAddress((void**)&H1,  g_H1);
    cudaGetSymbolAddress((void**)&X2,  g_X2);
    cudaGetSymbolAddress((void**)&AB,  g_AB);
    cudaGetSymbolAddress((void**)&G,   g_G);

    cudaFuncSetAttribute(attn_kernel,
                         cudaFuncAttributeMaxDynamicSharedMemorySize,
                         ATT_SMEM_BYTES);

    // 1) LN1
    ln_kernel<<<ROWS, 256>>>(hidden, ln1_g, ln1_b, X);
    // 2) QKV projection
    sgemm_kernel<0><<<dim3(NQKV/128, ROWS/128), 256>>>(X, Wqkv, nullptr, QKV,
                                                       ROWS, NQKV, DD);
    // 3) RoPE + scatter to [B,H,S,DH]
    rope_kernel<<<dim3(ROWS, HH), 128>>>(QKV, pos, Q, K, V);
    // 4) attention -> ctx [B,S,H*DH]
    attn_kernel<<<dim3(SS/64, HH, BB), 256, ATT_SMEM_BYTES>>>(Q, K, V, mask, CTX);
    // 5) Wo projection + residual add (h1)
    sgemm_kernel<1><<<dim3(DD/128, ROWS/128), 256>>>(CTX, Wo, hidden, H1,
                                                     ROWS, DD, DD);
    // 6) LN2
    ln_kernel<<<ROWS, 256>>>(H1, ln2_g, ln2_b, X2);
    // 7) fc_in
    sgemm_kernel<0><<<dim3(NFC/128, ROWS/128), 256>>>(X2, Wfc_in, nullptr, AB,
                                                      ROWS, NFC, DD);
    // 8) SwiGLU
    {
        const int total4 = ROWS * FFN / 4;
        swiglu_kernel<<<(total4 + 255)/256, 256>>>(AB, G);
    }
    // 9) fc_out + residual add (final output)
    sgemm_kernel<1><<<dim3(DD/128, ROWS/128), 256>>>(G, Wfc_out, H1, out,
                                                     ROWS, DD, FFN);
}

// round 3
// speedup vs baseline: 2.0188x; 2.0188x over previous
#include <cuda_runtime.h>
#include <cuda_bf16.h>
#include <math.h>
#include <stdint.h>

// ---------------------------------------------------------------------------
// Problem constants
// ---------------------------------------------------------------------------
#define BB   2
#define SS   2048
#define DD   2048
#define HH   16
#define DHH  128
#define FFN  5632
#define ROWS (BB*SS)           // 4096
#define NQKV (3*HH*DHH)        // 6144
#define NFC  (2*FFN)           // 11264

// ---------------------------------------------------------------------------
// Scratch (static device globals; allocation is forbidden)
// ---------------------------------------------------------------------------
__device__ float g_X  [ROWS*DD];     // LN1 out (tf32-rounded)
__device__ float g_QKV[ROWS*NQKV];   // qkv proj
__device__ float g_Q  [ROWS*DD];     // [B,H,S,DH]
__device__ float g_K  [ROWS*DD];
__device__ float g_V  [ROWS*DD];
__device__ float g_CTX[ROWS*DD];     // [B,S,H*DH] (tf32-rounded)
__device__ float g_H1 [ROWS*DD];     // residual 1
__device__ float g_X2 [ROWS*DD];     // LN2 out (tf32-rounded)
__device__ float g_AB [ROWS*NFC];    // fc_in out
__device__ float g_G  [ROWS*FFN];    // swiglu out (tf32-rounded)
// transposed weights [N,K] K-major, tf32-rounded
__device__ float g_WqkvT [NQKV*DD];
__device__ float g_WoT   [DD*DD];
__device__ float g_WfciT [NFC*DD];
__device__ float g_WfcoT [DD*FFN];

// ---------------------------------------------------------------------------
// Helpers
// ---------------------------------------------------------------------------
__device__ __forceinline__ float to_tf32(float x) {
    float o;
    asm("cvt.rna.tf32.f32 %0, %1;" : "=f"(o) : "f"(x));
    return o;
}

__device__ __forceinline__ uint32_t smem_u32(const void* p) {
    uint32_t a;
    asm("{ .reg .u64 t; cvta.to.shared.u64 t, %1; cvt.u32.u64 %0, t; }"
        : "=r"(a) : "l"(p));
    return a;
}

#define CP_ASYNC16(dst, src) \
    asm volatile("cp.async.cg.shared.global [%0], [%1], 16;" \
                 :: "r"(dst), "l"(src))
#define CP_COMMIT() asm volatile("cp.async.commit_group;" ::: "memory")
#define CP_WAIT1()  asm volatile("cp.async.wait_group 1;" ::: "memory")
#define CP_WAIT0()  asm volatile("cp.async.wait_group 0;" ::: "memory")

#define MMA_TF32(d, a, b)                                                  \
    asm volatile(                                                          \
        "mma.sync.aligned.m16n8k8.row.col.f32.tf32.tf32.f32 "              \
        "{%0,%1,%2,%3}, {%4,%5,%6,%7}, {%8,%9}, {%0,%1,%2,%3};"            \
        : "+f"((d)[0]), "+f"((d)[1]), "+f"((d)[2]), "+f"((d)[3])           \
        : "r"((a)[0]), "r"((a)[1]), "r"((a)[2]), "r"((a)[3]),              \
          "r"((b)[0]), "r"((b)[1]))

// ---------------------------------------------------------------------------
// Weight transpose + tf32 round: W[K,N] -> Wt[N,K]
// ---------------------------------------------------------------------------
__global__ void __launch_bounds__(256) transpose_rna(
    const float* __restrict__ W, float* __restrict__ Wt, int K, int N)
{
    __shared__ float t[32][33];
    const int tx = threadIdx.x, ty = threadIdx.y;     // 32 x 8
    const int n0 = blockIdx.x * 32, k0 = blockIdx.y * 32;
#pragma unroll
    for (int j = 0; j < 4; j++)
        t[ty + j*8][tx] = W[(size_t)(k0 + ty + j*8) * N + n0 + tx];
    __syncthreads();
#pragma unroll
    for (int j = 0; j < 4; j++)
        Wt[(size_t)(n0 + ty + j*8) * K + k0 + tx] = to_tf32(t[tx][ty + j*8]);
}

// ---------------------------------------------------------------------------
// TF32 mma.sync GEMM: C[M,N] = A[M,K] @ Bt[N,K]^T (+R)
// CTA tile 128x128x32, 8 warps (2M x 4N), warp tile 64x32.
// 3-stage cp.async pipeline. Smem rows padded to 36 floats (conflict-free).
// ---------------------------------------------------------------------------
#define BKk    32
#define AS_F   (128*36)
#define STAGE_F (2*AS_F)
#define GM_SMEM_BYTES (3*STAGE_F*4)     // 108 KB

template<int EPI>
__global__ void __launch_bounds__(256, 1) tgemm(
    const float* __restrict__ A, const float* __restrict__ Bt,
    const float* __restrict__ R, float* __restrict__ C,
    int K, int N)
{
    extern __shared__ float sm[];

    const int tid  = threadIdx.x;
    const int wid  = tid >> 5;
    const int lane = tid & 31;
    const int g    = lane >> 2;      // group id (row within frag)
    const int cc   = lane & 3;       // thread in group
    const int wm   = (wid & 1) * 64; // warp M offset
    const int wn   = (wid >> 1) * 32;// warp N offset

    const int m0 = blockIdx.y * 128;
    const int n0 = blockIdx.x * 128;

    const float* Ab = A  + (size_t)m0 * K;
    const float* Bb = Bt + (size_t)n0 * K;

    const int NC = K / BKk;

    // load one 128x32 A chunk + 128x32 B chunk into stage st
#define LOAD_STAGE(chunk, st) do {                                         \
        const uint32_t asw = smem_u32(sm + (st)*STAGE_F);                  \
        const uint32_t bsw = asw + AS_F*4;                                 \
        const int kt = (chunk) * BKk;                                      \
        _Pragma("unroll")                                                  \
        for (int j = 0; j < 4; j++) {                                      \
            const int f = tid + j * 256;                                   \
            const int row = f >> 3, c4 = f & 7;                            \
            CP_ASYNC16(asw + (uint32_t)(row*144 + c4*16),                  \
                       Ab + (size_t)row * K + kt + c4*4);                  \
            CP_ASYNC16(bsw + (uint32_t)(row*144 + c4*16),                  \
                       Bb + (size_t)row * K + kt + c4*4);                  \
        }                                                                  \
        CP_COMMIT();                                                       \
    } while (0)

    float acc[4][4][4];
#pragma unroll
    for (int mf = 0; mf < 4; mf++)
#pragma unroll
        for (int nf = 0; nf < 4; nf++)
#pragma unroll
            for (int q = 0; q < 4; q++) acc[mf][nf][q] = 0.f;

    LOAD_STAGE(0, 0);
    LOAD_STAGE(1, 1);

    for (int i = 0; i < NC; i++) {
        if (i == NC - 1) CP_WAIT0(); else CP_WAIT1();
        __syncthreads();
        if (i + 2 < NC) LOAD_STAGE(i + 2, (i + 2) % 3);

        const uint32_t* Asu = (const uint32_t*)(sm + (i % 3) * STAGE_F);
        const uint32_t* Bsu = Asu + AS_F;

#pragma unroll
        for (int ks = 0; ks < 4; ks++) {
            uint32_t a[4][4], b[4][2];
            const int col = ks * 8 + cc;
#pragma unroll
            for (int mf = 0; mf < 4; mf++) {
                const int r0 = wm + mf * 16 + g;
                a[mf][0] = Asu[r0*36 + col];
                a[mf][1] = Asu[(r0+8)*36 + col];
                a[mf][2] = Asu[r0*36 + col + 4];
                a[mf][3] = Asu[(r0+8)*36 + col + 4];
            }
#pragma unroll
            for (int nf = 0; nf < 4; nf++) {
                const int n = wn + nf * 8 + g;
                b[nf][0] = Bsu[n*36 + col];
                b[nf][1] = Bsu[n*36 + col + 4];
            }
#pragma unroll
            for (int mf = 0; mf < 4; mf++)
#pragma unroll
                for (int nf = 0; nf < 4; nf++)
                    MMA_TF32(acc[mf][nf], a[mf], b[nf]);
        }
    }
#undef LOAD_STAGE

    // epilogue
#pragma unroll
    for (int mf = 0; mf < 4; mf++) {
#pragma unroll
        for (int nf = 0; nf < 4; nf++) {
            const int row = m0 + wm + mf * 16 + g;
            const int col = n0 + wn + nf * 8 + cc * 2;
            const size_t o0 = (size_t)row * N + col;
            const size_t o1 = (size_t)(row + 8) * N + col;
            float2 v0 = { acc[mf][nf][0], acc[mf][nf][1] };
            float2 v1 = { acc[mf][nf][2], acc[mf][nf][3] };
            if (EPI == 1) {
                float2 r0 = *(const float2*)&R[o0];
                float2 r1 = *(const float2*)&R[o1];
                v0.x += r0.x; v0.y += r0.y;
                v1.x += r1.x; v1.y += r1.y;
            }
            *(float2*)&C[o0] = v0;
            *(float2*)&C[o1] = v1;
        }
    }
}

// ---------------------------------------------------------------------------
// LayerNorm: one block per row (2048 cols), 256 threads; output tf32-rounded
// ---------------------------------------------------------------------------
__global__ void __launch_bounds__(256) ln_kernel(
    const float* __restrict__ X, const float* __restrict__ g,
    const float* __restrict__ b, float* __restrict__ Y)
{
    const int tid = threadIdx.x;
    const float* x = X + (size_t)blockIdx.x * DD;
    float* y = Y + (size_t)blockIdx.x * DD;

    float v[8];
    *(float4*)&v[0] = *(const float4*)&x[tid*8];
    *(float4*)&v[4] = *(const float4*)&x[tid*8 + 4];

    float s = 0.f, sq = 0.f;
#pragma unroll
    for (int i = 0; i < 8; i++) { s += v[i]; sq += v[i]*v[i]; }
#pragma unroll
    for (int o = 16; o; o >>= 1) {
        s  += __shfl_xor_sync(0xffffffffu, s,  o);
        sq += __shfl_xor_sync(0xffffffffu, sq, o);
    }
    __shared__ float red[2][8];
    __shared__ float stats[2];
    const int w = tid >> 5, l = tid & 31;
    if (l == 0) { red[0][w] = s; red[1][w] = sq; }
    __syncthreads();
    if (tid == 0) {
        float S = 0.f, SQ = 0.f;
#pragma unroll
        for (int i = 0; i < 8; i++) { S += red[0][i]; SQ += red[1][i]; }
        const float mean = S * (1.0f/DD);
        const float var  = SQ * (1.0f/DD) - mean*mean;
        stats[0] = mean;
        stats[1] = rsqrtf(var + 1e-5f);
    }
    __syncthreads();
    const float mean = stats[0], rstd = stats[1];

    float gv[8], bv[8];
    *(float4*)&gv[0] = *(const float4*)&g[tid*8];
    *(float4*)&gv[4] = *(const float4*)&g[tid*8+4];
    *(float4*)&bv[0] = *(const float4*)&b[tid*8];
    *(float4*)&bv[4] = *(const float4*)&b[tid*8+4];
#pragma unroll
    for (int i = 0; i < 8; i++)
        v[i] = to_tf32((v[i] - mean) * rstd * gv[i] + bv[i]);
    *(float4*)&y[tid*8]     = *(float4*)&v[0];
    *(float4*)&y[tid*8 + 4] = *(float4*)&v[4];
}

// ---------------------------------------------------------------------------
// RoPE + scatter: QKV[B,S,H,3*DH] -> Q/K/V [B,H,S,DH] (rope on Q,K)
// ---------------------------------------------------------------------------
__global__ void __launch_bounds__(128) rope_kernel(
    const float* __restrict__ QKV, const int* __restrict__ pos_ids,
    float* __restrict__ Q, float* __restrict__ K, float* __restrict__ V)
{
    const int bs = blockIdx.x;
    const int h  = blockIdx.y;
    const int d  = threadIdx.x;
    const int pos = pos_ids[bs];

    const float* row = QKV + (size_t)bs * NQKV + h * (3*DHH);
    const float q = row[d];
    const float k = row[DHH + d];
    const float v = row[2*DHH + d];

    const int j = d & 63;
    const float inv = 1.0f / powf(10000.0f, (float)(2*j) * (1.0f/128.0f));
    const float fr = (float)pos * inv;
    const float sn = sinf(fr), cs = cosf(fr);

    float qo, ko;
    if (d < 64) {
        qo = q * cs - row[d + 64] * sn;
        ko = k * cs - row[DHH + d + 64] * sn;
    } else {
        qo = q * cs + row[d - 64] * sn;
        ko = k * cs + row[DHH + d - 64] * sn;
    }
    const int b = bs >> 11, s = bs & 2047;
    const size_t o = (((size_t)(b*HH + h)) * SS + s) * DHH + d;
    Q[o] = qo; K[o] = ko; V[o] = v;
}

// ---------------------------------------------------------------------------
// Flash attention (fp32)
// ---------------------------------------------------------------------------
#define ATT_SMEM_FLOATS (128*68 + 128*68 + 64*128 + 64*68)
#define ATT_SMEM_BYTES  (ATT_SMEM_FLOATS * 4)

__global__ void __launch_bounds__(256) attn_kernel(
    const float* __restrict__ Q, const float* __restrict__ K,
    const float* __restrict__ V, const unsigned char* __restrict__ mask,
    float* __restrict__ CTX)
{
    extern __shared__ float smf[];
    float* Qs = smf;
    float* Ks = Qs + 128*68;
    float* Vs = Ks + 128*68;
    float* Ps = Vs + 64*128;

    const int tid = threadIdx.x;
    const int tx = tid & 15, ty = tid >> 4;
    const int qt = blockIdx.x, h = blockIdx.y, b = blockIdx.z;

    const size_t headoff = ((size_t)(b*HH + h)) * SS * DHH;
    const float* Qg = Q + headoff + (size_t)qt * 64 * DHH;

    for (int f = tid; f < 2048; f += 256) {
        const int r = f >> 5;
        const int k = (f & 31) << 2;
        float4 t = *(const float4*)&Qg[r*DHH + k];
        Qs[(k+0)*68 + r] = t.x; Qs[(k+1)*68 + r] = t.y;
        Qs[(k+2)*68 + r] = t.z; Qs[(k+3)*68 + r] = t.w;
    }

    float m_run[4], l_run[4], O[4][8];
#pragma unroll
    for (int i = 0; i < 4; i++) {
        m_run[i] = -1e30f; l_run[i] = 0.f;
#pragma unroll
        for (int c = 0; c < 8; c++) O[i][c] = 0.f;
    }
    const float scale = 0.08838834764831845f;
    const unsigned char* mrow = mask + (size_t)b * SS * SS;
    const int qbase = qt * 64 + ty * 4;

    for (int kt = 0; kt < SS; kt += 64) {
        __syncthreads();
        const float* Kg = K + headoff + (size_t)kt * DHH;
        const float* Vg = V + headoff + (size_t)kt * DHH;
        for (int f = tid; f < 2048; f += 256) {
            const int r = f >> 5;
            const int k = (f & 31) << 2;
            float4 t = *(const float4*)&Kg[r*DHH + k];
            Ks[(k+0)*68 + r] = t.x; Ks[(k+1)*68 + r] = t.y;
            Ks[(k+2)*68 + r] = t.z; Ks[(k+3)*68 + r] = t.w;
            ((float4*)Vs)[f] = *(const float4*)&Vg[r*DHH + k];
        }
        __syncthreads();

        float s[4][4];
#pragma unroll
        for (int i = 0; i < 4; i++)
#pragma unroll
            for (int j = 0; j < 4; j++) s[i][j] = 0.f;

#pragma unroll 4
        for (int k = 0; k < 128; k++) {
            float4 qv = *(float4*)&Qs[k*68 + ty*4];
            float4 kv = *(float4*)&Ks[k*68 + tx*4];
            const float q0[4] = {qv.x, qv.y, qv.z, qv.w};
            const float k0[4] = {kv.x, kv.y, kv.z, kv.w};
#pragma unroll
            for (int i = 0; i < 4; i++)
#pragma unroll
                for (int j = 0; j < 4; j++) s[i][j] += q0[i] * k0[j];
        }

#pragma unroll
        for (int i = 0; i < 4; i++) {
#pragma unroll
            for (int j = 0; j < 4; j++) {
                float sv = s[i][j] * scale;
                if (mrow[(size_t)(qbase + i) * SS + kt + tx*4 + j]) sv = -10000.f;
                s[i][j] = sv;
            }
            float mt = fmaxf(fmaxf(s[i][0], s[i][1]), fmaxf(s[i][2], s[i][3]));
#pragma unroll
            for (int o = 8; o; o >>= 1) mt = fmaxf(mt, __shfl_xor_sync(0xffffffffu, mt, o));
            const float mnew = fmaxf(m_run[i], mt);
            float p[4], sum = 0.f;
#pragma unroll
            for (int j = 0; j < 4; j++) { p[j] = expf(s[i][j] - mnew); sum += p[j]; }
#pragma unroll
            for (int o = 8; o; o >>= 1) sum += __shfl_xor_sync(0xffffffffu, sum, o);
            const float cf = expf(m_run[i] - mnew);
            l_run[i] = l_run[i] * cf + sum;
            m_run[i] = mnew;
#pragma unroll
            for (int c = 0; c < 8; c++) O[i][c] *= cf;
            Ps[(ty*4 + i)*68 + tx*4 + 0] = p[0];
            Ps[(ty*4 + i)*68 + tx*4 + 1] = p[1];
            Ps[(ty*4 + i)*68 + tx*4 + 2] = p[2];
            Ps[(ty*4 + i)*68 + tx*4 + 3] = p[3];
        }
        __syncthreads();

#pragma unroll 2
        for (int jj = 0; jj < 64; jj++) {
            float4 v0 = *(float4*)&Vs[jj*128 + tx*8];
            float4 v1 = *(float4*)&Vs[jj*128 + tx*8 + 4];
            const float vv[8] = {v0.x, v0.y, v0.z, v0.w, v1.x, v1.y, v1.z, v1.w};
#pragma unroll
            for (int i = 0; i < 4; i++) {
                const float p = Ps[(ty*4 + i)*68 + jj];
#pragma unroll
                for (int c = 0; c < 8; c++) O[i][c] += p * vv[c];
            }
        }
    }

    // normalize, tf32-round (feeds Wo GEMM), write ctx [B,S,H*DH]
#pragma unroll
    for (int i = 0; i < 4; i++) {
        const float inv = 1.0f / l_run[i];
        float4 o0 = {to_tf32(O[i][0]*inv), to_tf32(O[i][1]*inv),
                     to_tf32(O[i][2]*inv), to_tf32(O[i][3]*inv)};
        float4 o1 = {to_tf32(O[i][4]*inv), to_tf32(O[i][5]*inv),
                     to_tf32(O[i][6]*inv), to_tf32(O[i][7]*inv)};
        const size_t off = ((size_t)(b*SS + qbase + i)) * DD + h*DHH + tx*8;
        *(float4*)&CTX[off]     = o0;
        *(float4*)&CTX[off + 4] = o1;
    }
}

// ---------------------------------------------------------------------------
// SwiGLU: g = silu(a) * b, tf32-rounded output (feeds fc_out GEMM)
// ---------------------------------------------------------------------------
__global__ void __launch_bounds__(256) swiglu_kernel(
    const float* __restrict__ AB, float* __restrict__ G)
{
    const int idx = blockIdx.x * blockDim.x + threadIdx.x;
    const int total4 = ROWS * FFN / 4;
    if (idx >= total4) return;
    const int e = idx * 4;
    const int r = e / FFN;
    const int c = e - r * FFN;
    const float* row = AB + (size_t)r * NFC;
    float4 a = *(const float4*)&row[c];
    float4 bb = *(const float4*)&row[FFN + c];
    float4 o;
    o.x = to_tf32(a.x / (1.0f + expf(-a.x)) * bb.x);
    o.y = to_tf32(a.y / (1.0f + expf(-a.y)) * bb.y);
    o.z = to_tf32(a.z / (1.0f + expf(-a.z)) * bb.z);
    o.w = to_tf32(a.w / (1.0f + expf(-a.w)) * bb.w);
    *(float4*)&G[(size_t)r * FFN + c] = o;
}

// ---------------------------------------------------------------------------
// Launch
// ---------------------------------------------------------------------------
extern "C" void kernel_launch(void* const* d_in, const int* in_sizes, int n_in,
                              void* d_out, int out_size)
{
    const float*         hidden  = (const float*)d_in[0];
    const unsigned char* mask    = (const unsigned char*)d_in[1];
    const int*           pos     = (const int*)d_in[2];
    const float*         ln1_g   = (const float*)d_in[3];
    const float*         ln1_b   = (const float*)d_in[4];
    const float*         Wqkv    = (const float*)d_in[5];
    const float*         Wo      = (const float*)d_in[6];
    const float*         ln2_g   = (const float*)d_in[7];
    const float*         ln2_b   = (const float*)d_in[8];
    const float*         Wfc_in  = (const float*)d_in[9];
    const float*         Wfc_out = (const float*)d_in[10];
    float*               out     = (float*)d_out;

    float *X, *QKV, *Q, *K, *V, *CTX, *H1, *X2, *AB, *G;
    float *WqkvT, *WoT, *WfciT, *WfcoT;
    cudaGetSymbolAddress((void**)&X,     g_X);
    cudaGetSymbolAddress((void**)&QKV,   g_QKV);
    cudaGetSymbolAddress((void**)&Q,     g_Q);
    cudaGetSymbolAddress((void**)&K,     g_K);
    cudaGetSymbolAddress((void**)&V,     g_V);
    cudaGetSymbolAddress((void**)&CTX,   g_CTX);
    cudaGetSymbolAddress((void**)&H1,    g_H1);
    cudaGetSymbolAddress((void**)&X2,    g_X2);
    cudaGetSymbolAddress((void**)&AB,    g_AB);
    cudaGetSymbolAddress((void**)&G,     g_G);
    cudaGetSymbolAddress((void**)&WqkvT, g_WqkvT);
    cudaGetSymbolAddress((void**)&WoT,   g_WoT);
    cudaGetSymbolAddress((void**)&WfciT, g_WfciT);
    cudaGetSymbolAddress((void**)&WfcoT, g_WfcoT);

    cudaFuncSetAttribute(attn_kernel,
                         cudaFuncAttributeMaxDynamicSharedMemorySize,
                         ATT_SMEM_BYTES);
    cudaFuncSetAttribute(tgemm<0>,
                         cudaFuncAttributeMaxDynamicSharedMemorySize,
                         GM_SMEM_BYTES);
    cudaFuncSetAttribute(tgemm<1>,
                         cudaFuncAttributeMaxDynamicSharedMemorySize,
                         GM_SMEM_BYTES);

    // 0) transpose + tf32-round weights to [N,K]
    transpose_rna<<<dim3(NQKV/32, DD/32),  dim3(32,8)>>>(Wqkv,    WqkvT, DD,  NQKV);
    transpose_rna<<<dim3(DD/32,   DD/32),  dim3(32,8)>>>(Wo,      WoT,   DD,  DD);
    transpose_rna<<<dim3(NFC/32,  DD/32),  dim3(32,8)>>>(Wfc_in,  WfciT, DD,  NFC);
    transpose_rna<<<dim3(DD/32,   FFN/32), dim3(32,8)>>>(Wfc_out, WfcoT, FFN, DD);

    // 1) LN1
    ln_kernel<<<ROWS, 256>>>(hidden, ln1_g, ln1_b, X);
    // 2) QKV projection (tf32 mma)
    tgemm<0><<<dim3(NQKV/128, ROWS/128), 256, GM_SMEM_BYTES>>>(
        X, WqkvT, nullptr, QKV, DD, NQKV);
    // 3) RoPE + scatter
    rope_kernel<<<dim3(ROWS, HH), 128>>>(QKV, pos, Q, K, V);
    // 4) attention -> ctx
    attn_kernel<<<dim3(SS/64, HH, BB), 256, ATT_SMEM_BYTES>>>(Q, K, V, mask, CTX);
    // 5) Wo projection + residual
    tgemm<1><<<dim3(DD/128, ROWS/128), 256, GM_SMEM_BYTES>>>(
        CTX, WoT, hidden, H1, DD, DD);
    // 6) LN2
    ln_kernel<<<ROWS, 256>>>(H1, ln2_g, ln2_b, X2);
    // 7) fc_in
    tgemm<0><<<dim3(NFC/128, ROWS/128), 256, GM_SMEM_BYTES>>>(
        X2, WfciT, nullptr, AB, DD, NFC);
    // 8) SwiGLU
    {
        const int total4 = ROWS * FFN / 4;
        swiglu_kernel<<<(total4 + 255)/256, 256>>>(AB, G);
    }
    // 9) fc_out + residual (final output)
    tgemm<1><<<dim3(DD/128, ROWS/128), 256, GM_SMEM_BYTES>>>(
        G, WfcoT, H1, out, FFN, DD);
}

// round 4
// speedup vs baseline: 2.9744x; 1.4734x over previous
#include <cuda_runtime.h>
#include <cuda_bf16.h>
#include <math.h>
#include <stdint.h>

// ---------------------------------------------------------------------------
// Problem constants
// ---------------------------------------------------------------------------
#define BB   2
#define SS   2048
#define DD   2048
#define HH   16
#define DHH  128
#define FFN  5632
#define ROWS (BB*SS)           // 4096
#define NQKV (3*HH*DHH)        // 6144
#define NFC  (2*FFN)           // 11264

// ---------------------------------------------------------------------------
// Scratch (static device globals; allocation is forbidden)
// ---------------------------------------------------------------------------
__device__ float g_X  [ROWS*DD];     // LN1 out (tf32-rounded)
__device__ float g_QKV[ROWS*NQKV];   // qkv proj
__device__ float g_Q  [ROWS*DD];     // [B,H,S,DH] tf32-rounded
__device__ float g_K  [ROWS*DD];
__device__ float g_V  [ROWS*DD];
__device__ float g_CTX[ROWS*DD];     // [B,S,H*DH] (tf32-rounded)
__device__ float g_H1 [ROWS*DD];     // residual 1
__device__ float g_X2 [ROWS*DD];     // LN2 out (tf32-rounded)
__device__ float g_AB [ROWS*NFC];    // fc_in out
__device__ float g_G  [ROWS*FFN];    // swiglu out (tf32-rounded)
// transposed weights [N,K] K-major, tf32-rounded
__device__ float g_WqkvT [NQKV*DD];
__device__ float g_WoT   [DD*DD];
__device__ float g_WfciT [NFC*DD];
__device__ float g_WfcoT [DD*FFN];

// ---------------------------------------------------------------------------
// Helpers
// ---------------------------------------------------------------------------
__device__ __forceinline__ float to_tf32(float x) {
    float o;
    asm("cvt.rna.tf32.f32 %0, %1;" : "=f"(o) : "f"(x));
    return o;
}

__device__ __forceinline__ uint32_t smem_u32(const void* p) {
    uint32_t a;
    asm("{ .reg .u64 t; cvta.to.shared.u64 t, %1; cvt.u32.u64 %0, t; }"
        : "=r"(a) : "l"(p));
    return a;
}

#define CP_ASYNC16(dst, src) \
    asm volatile("cp.async.cg.shared.global [%0], [%1], 16;" \
                 :: "r"(dst), "l"(src))
#define CP_COMMIT() asm volatile("cp.async.commit_group;" ::: "memory")
#define CP_WAIT1()  asm volatile("cp.async.wait_group 1;" ::: "memory")
#define CP_WAIT0()  asm volatile("cp.async.wait_group 0;" ::: "memory")

#define MMA_TF32(d, a, b)                                                  \
    asm volatile(                                                          \
        "mma.sync.aligned.m16n8k8.row.col.f32.tf32.tf32.f32 "              \
        "{%0,%1,%2,%3}, {%4,%5,%6,%7}, {%8,%9}, {%0,%1,%2,%3};"            \
        : "+f"((d)[0]), "+f"((d)[1]), "+f"((d)[2]), "+f"((d)[3])           \
        : "r"((a)[0]), "r"((a)[1]), "r"((a)[2]), "r"((a)[3]),              \
          "r"((b)[0]), "r"((b)[1]))

// ---------------------------------------------------------------------------
// Weight transpose + tf32 round: W[K,N] -> Wt[N,K]
// ---------------------------------------------------------------------------
__global__ void __launch_bounds__(256) transpose_rna(
    const float* __restrict__ W, float* __restrict__ Wt, int K, int N)
{
    __shared__ float t[32][33];
    const int tx = threadIdx.x, ty = threadIdx.y;     // 32 x 8
    const int n0 = blockIdx.x * 32, k0 = blockIdx.y * 32;
#pragma unroll
    for (int j = 0; j < 4; j++)
        t[ty + j*8][tx] = W[(size_t)(k0 + ty + j*8) * N + n0 + tx];
    __syncthreads();
#pragma unroll
    for (int j = 0; j < 4; j++)
        Wt[(size_t)(n0 + ty + j*8) * K + k0 + tx] = to_tf32(t[tx][ty + j*8]);
}

// ---------------------------------------------------------------------------
// TF32 mma.sync GEMM: C[M,N] = A[M,K] @ Bt[N,K]^T (+R)
// CTA tile 128x128x32, 8 warps (2M x 4N), warp tile 64x32.
// ---------------------------------------------------------------------------
#define BKk    32
#define AS_F   (128*36)
#define STAGE_F (2*AS_F)
#define GM_SMEM_BYTES (3*STAGE_F*4)     // 108 KB

template<int EPI>
__global__ void __launch_bounds__(256, 1) tgemm(
    const float* __restrict__ A, const float* __restrict__ Bt,
    const float* __restrict__ R, float* __restrict__ C,
    int K, int N)
{
    extern __shared__ float sm[];

    const int tid  = threadIdx.x;
    const int wid  = tid >> 5;
    const int lane = tid & 31;
    const int g    = lane >> 2;
    const int cc   = lane & 3;
    const int wm   = (wid & 1) * 64;
    const int wn   = (wid >> 1) * 32;

    const int m0 = blockIdx.y * 128;
    const int n0 = blockIdx.x * 128;

    const float* Ab = A  + (size_t)m0 * K;
    const float* Bb = Bt + (size_t)n0 * K;

    const int NC = K / BKk;

#define LOAD_STAGE(chunk, st) do {                                         \
        const uint32_t asw = smem_u32(sm + (st)*STAGE_F);                  \
        const uint32_t bsw = asw + AS_F*4;                                 \
        const int kt = (chunk) * BKk;                                      \
        _Pragma("unroll")                                                  \
        for (int j = 0; j < 4; j++) {                                      \
            const int f = tid + j * 256;                                   \
            const int row = f >> 3, c4 = f & 7;                            \
            CP_ASYNC16(asw + (uint32_t)(row*144 + c4*16),                  \
                       Ab + (size_t)row * K + kt + c4*4);                  \
            CP_ASYNC16(bsw + (uint32_t)(row*144 + c4*16),                  \
                       Bb + (size_t)row * K + kt + c4*4);                  \
        }                                                                  \
        CP_COMMIT();                                                       \
    } while (0)

    float acc[4][4][4];
#pragma unroll
    for (int mf = 0; mf < 4; mf++)
#pragma unroll
        for (int nf = 0; nf < 4; nf++)
#pragma unroll
            for (int q = 0; q < 4; q++) acc[mf][nf][q] = 0.f;

    LOAD_STAGE(0, 0);
    LOAD_STAGE(1, 1);

    for (int i = 0; i < NC; i++) {
        if (i == NC - 1) CP_WAIT0(); else CP_WAIT1();
        __syncthreads();
        if (i + 2 < NC) LOAD_STAGE(i + 2, (i + 2) % 3);

        const uint32_t* Asu = (const uint32_t*)(sm + (i % 3) * STAGE_F);
        const uint32_t* Bsu = Asu + AS_F;

#pragma unroll
        for (int ks = 0; ks < 4; ks++) {
            uint32_t a[4][4], b[4][2];
            const int col = ks * 8 + cc;
#pragma unroll
            for (int mf = 0; mf < 4; mf++) {
                const int r0 = wm + mf * 16 + g;
                a[mf][0] = Asu[r0*36 + col];
                a[mf][1] = Asu[(r0+8)*36 + col];
                a[mf][2] = Asu[r0*36 + col + 4];
                a[mf][3] = Asu[(r0+8)*36 + col + 4];
            }
#pragma unroll
            for (int nf = 0; nf < 4; nf++) {
                const int n = wn + nf * 8 + g;
                b[nf][0] = Bsu[n*36 + col];
                b[nf][1] = Bsu[n*36 + col + 4];
            }
#pragma unroll
            for (int mf = 0; mf < 4; mf++)
#pragma unroll
                for (int nf = 0; nf < 4; nf++)
                    MMA_TF32(acc[mf][nf], a[mf], b[nf]);
        }
    }
#undef LOAD_STAGE

#pragma unroll
    for (int mf = 0; mf < 4; mf++) {
#pragma unroll
        for (int nf = 0; nf < 4; nf++) {
            const int row = m0 + wm + mf * 16 + g;
            const int col = n0 + wn + nf * 8 + cc * 2;
            const size_t o0 = (size_t)row * N + col;
            const size_t o1 = (size_t)(row + 8) * N + col;
            float2 v0 = { acc[mf][nf][0], acc[mf][nf][1] };
            float2 v1 = { acc[mf][nf][2], acc[mf][nf][3] };
            if (EPI == 1) {
                float2 r0 = *(const float2*)&R[o0];
                float2 r1 = *(const float2*)&R[o1];
                v0.x += r0.x; v0.y += r0.y;
                v1.x += r1.x; v1.y += r1.y;
            }
            *(float2*)&C[o0] = v0;
            *(float2*)&C[o1] = v1;
        }
    }
}

// ---------------------------------------------------------------------------
// LayerNorm (tf32-rounded output)
// ---------------------------------------------------------------------------
__global__ void __launch_bounds__(256) ln_kernel(
    const float* __restrict__ X, const float* __restrict__ g,
    const float* __restrict__ b, float* __restrict__ Y)
{
    const int tid = threadIdx.x;
    const float* x = X + (size_t)blockIdx.x * DD;
    float* y = Y + (size_t)blockIdx.x * DD;

    float v[8];
    *(float4*)&v[0] = *(const float4*)&x[tid*8];
    *(float4*)&v[4] = *(const float4*)&x[tid*8 + 4];

    float s = 0.f, sq = 0.f;
#pragma unroll
    for (int i = 0; i < 8; i++) { s += v[i]; sq += v[i]*v[i]; }
#pragma unroll
    for (int o = 16; o; o >>= 1) {
        s  += __shfl_xor_sync(0xffffffffu, s,  o);
        sq += __shfl_xor_sync(0xffffffffu, sq, o);
    }
    __shared__ float red[2][8];
    __shared__ float stats[2];
    const int w = tid >> 5, l = tid & 31;
    if (l == 0) { red[0][w] = s; red[1][w] = sq; }
    __syncthreads();
    if (tid == 0) {
        float S = 0.f, SQ = 0.f;
#pragma unroll
        for (int i = 0; i < 8; i++) { S += red[0][i]; SQ += red[1][i]; }
        const float mean = S * (1.0f/DD);
        const float var  = SQ * (1.0f/DD) - mean*mean;
        stats[0] = mean;
        stats[1] = rsqrtf(var + 1e-5f);
    }
    __syncthreads();
    const float mean = stats[0], rstd = stats[1];

    float gv[8], bv[8];
    *(float4*)&gv[0] = *(const float4*)&g[tid*8];
    *(float4*)&gv[4] = *(const float4*)&g[tid*8+4];
    *(float4*)&bv[0] = *(const float4*)&b[tid*8];
    *(float4*)&bv[4] = *(const float4*)&b[tid*8+4];
#pragma unroll
    for (int i = 0; i < 8; i++)
        v[i] = to_tf32((v[i] - mean) * rstd * gv[i] + bv[i]);
    *(float4*)&y[tid*8]     = *(float4*)&v[0];
    *(float4*)&y[tid*8 + 4] = *(float4*)&v[4];
}

// ---------------------------------------------------------------------------
// RoPE + scatter: QKV[B,S,H,3*DH] -> Q/K/V [B,H,S,DH]; outputs tf32-rounded
// ---------------------------------------------------------------------------
__global__ void __launch_bounds__(128) rope_kernel(
    const float* __restrict__ QKV, const int* __restrict__ pos_ids,
    float* __restrict__ Q, float* __restrict__ K, float* __restrict__ V)
{
    const int bs = blockIdx.x;
    const int h  = blockIdx.y;
    const int d  = threadIdx.x;
    const int pos = pos_ids[bs];

    const float* row = QKV + (size_t)bs * NQKV + h * (3*DHH);
    const float q = row[d];
    const float k = row[DHH + d];
    const float v = row[2*DHH + d];

    const int j = d & 63;
    const float inv = 1.0f / powf(10000.0f, (float)(2*j) * (1.0f/128.0f));
    const float fr = (float)pos * inv;
    const float sn = sinf(fr), cs = cosf(fr);

    float qo, ko;
    if (d < 64) {
        qo = q * cs - row[d + 64] * sn;
        ko = k * cs - row[DHH + d + 64] * sn;
    } else {
        qo = q * cs + row[d - 64] * sn;
        ko = k * cs + row[DHH + d - 64] * sn;
    }
    const int b = bs >> 11, s = bs & 2047;
    const size_t o = (((size_t)(b*HH + h)) * SS + s) * DHH + d;
    Q[o] = to_tf32(qo); K[o] = to_tf32(ko); V[o] = to_tf32(v);
}

// ---------------------------------------------------------------------------
// Flash attention, tf32 mma.sync.
// Q tile 128 rows (8 warps x 16 rows), K/V tiles 64, online softmax.
// Smem strides chosen so fragment gathers are bank-conflict free.
// ---------------------------------------------------------------------------
#define AQ_STR 132
#define AK_STR 136
#define AV_STR 136
#define AP_STR 68
#define AT_SMEM_FLOATS (128*AQ_STR + 64*AK_STR + 64*AV_STR + 128*AP_STR)
#define AT_SMEM_BYTES  (AT_SMEM_FLOATS*4)     // 172032

__global__ void __launch_bounds__(256, 1) attn_kernel(
    const float* __restrict__ Q, const float* __restrict__ K,
    const float* __restrict__ V, const unsigned char* __restrict__ mask,
    float* __restrict__ CTX)
{
    extern __shared__ float smf[];
    float* Qs = smf;                       // [128][AQ_STR]  (m, k=dh)
    float* Ks = Qs + 128*AQ_STR;           // [64][AK_STR]   (kv, dh)
    float* Vs = Ks + 64*AK_STR;            // [64][AV_STR]   (kv, dh)
    float* Ps = Vs + 64*AV_STR;            // [128][AP_STR]  (m, kv)

    const int tid  = threadIdx.x;
    const int wid  = tid >> 5;
    const int lane = tid & 31;
    const int g    = lane >> 2;
    const int cc   = lane & 3;
    const int wm   = wid * 16;

    const int qt = blockIdx.x, h = blockIdx.y, b = blockIdx.z;
    const size_t headoff = ((size_t)(b*HH + h)) * SS * DHH;
    const float* Qg = Q + headoff + (size_t)qt * 128 * DHH;

    // load Q tile 128x128 -> Qs
#pragma unroll
    for (int j = 0; j < 16; j++) {
        const int f = tid + j * 256;
        const int r = f >> 5, k4 = (f & 31) << 2;
        *(float4*)&Qs[r*AQ_STR + k4] = *(const float4*)&Qg[r*DHH + k4];
    }

    float m0r = -1e30f, m1r = -1e30f, l0r = 0.f, l1r = 0.f;
    float O[16][4];
#pragma unroll
    for (int nf = 0; nf < 16; nf++)
#pragma unroll
        for (int q = 0; q < 4; q++) O[nf][q] = 0.f;

    const float scale = 0.08838834764831845f;   // 1/sqrt(128)
    const unsigned char* mrow = mask + (size_t)b * SS * SS;
    const int qg0 = qt * 128 + wm + g;
    const int qg8 = qg0 + 8;

    const uint32_t* Qsu = (const uint32_t*)Qs;
    const uint32_t* Ksu = (const uint32_t*)Ks;
    const uint32_t* Vsu = (const uint32_t*)Vs;
    const uint32_t* Psu = (const uint32_t*)Ps;

    for (int kt = 0; kt < SS; kt += 64) {
        __syncthreads();   // previous tile fully consumed
        const float* Kg = K + headoff + (size_t)kt * DHH;
        const float* Vg = V + headoff + (size_t)kt * DHH;
#pragma unroll
        for (int j = 0; j < 8; j++) {
            const int f = tid + j * 256;
            const int r = f >> 5, k4 = (f & 31) << 2;
            *(float4*)&Ks[r*AK_STR + k4] = *(const float4*)&Kg[r*DHH + k4];
            *(float4*)&Vs[r*AV_STR + k4] = *(const float4*)&Vg[r*DHH + k4];
        }
        // prefetch mask bytes for this tile (2 rows x 8 col-pairs per thread)
        unsigned short mRa[8], mRb[8];
        {
            const unsigned char* mpA = mrow + (size_t)qg0 * SS + kt + 2*cc;
            const unsigned char* mpB = mrow + (size_t)qg8 * SS + kt + 2*cc;
#pragma unroll
            for (int nf = 0; nf < 8; nf++) {
                mRa[nf] = *(const unsigned short*)(mpA + nf*8);
                mRb[nf] = *(const unsigned short*)(mpB + nf*8);
            }
        }
        __syncthreads();

        // ---- S = Q @ K^T : per warp 16x64 ----
        float s[8][4];
#pragma unroll
        for (int nf = 0; nf < 8; nf++)
#pragma unroll
            for (int q = 0; q < 4; q++) s[nf][q] = 0.f;

#pragma unroll
        for (int ks = 0; ks < 16; ks++) {
            const int col = ks*8 + cc;
            uint32_t a[4], bb[8][2];
            a[0] = Qsu[(wm+g)*AQ_STR + col];
            a[1] = Qsu[(wm+g+8)*AQ_STR + col];
            a[2] = Qsu[(wm+g)*AQ_STR + col + 4];
            a[3] = Qsu[(wm+g+8)*AQ_STR + col + 4];
#pragma unroll
            for (int nf = 0; nf < 8; nf++) {
                bb[nf][0] = Ksu[(nf*8+g)*AK_STR + col];
                bb[nf][1] = Ksu[(nf*8+g)*AK_STR + col + 4];
            }
#pragma unroll
            for (int nf = 0; nf < 8; nf++)
                MMA_TF32(s[nf], a, bb[nf]);
        }

        // ---- softmax (online) ----
        float rmax0 = -1e30f, rmax1 = -1e30f;
#pragma unroll
        for (int nf = 0; nf < 8; nf++) {
            float s0 = s[nf][0]*scale, s1 = s[nf][1]*scale;
            float s2 = s[nf][2]*scale, s3 = s[nf][3]*scale;
            if (mRa[nf] & 0x00ffu) s0 = -10000.f;
            if (mRa[nf] & 0xff00u) s1 = -10000.f;
            if (mRb[nf] & 0x00ffu) s2 = -10000.f;
            if (mRb[nf] & 0xff00u) s3 = -10000.f;
            s[nf][0] = s0; s[nf][1] = s1; s[nf][2] = s2; s[nf][3] = s3;
            rmax0 = fmaxf(rmax0, fmaxf(s0, s1));
            rmax1 = fmaxf(rmax1, fmaxf(s2, s3));
        }
        rmax0 = fmaxf(rmax0, __shfl_xor_sync(0xffffffffu, rmax0, 1));
        rmax0 = fmaxf(rmax0, __shfl_xor_sync(0xffffffffu, rmax0, 2));
        rmax1 = fmaxf(rmax1, __shfl_xor_sync(0xffffffffu, rmax1, 1));
        rmax1 = fmaxf(rmax1, __shfl_xor_sync(0xffffffffu, rmax1, 2));

        const float mn0 = fmaxf(m0r, rmax0);
        const float mn1 = fmaxf(m1r, rmax1);
        const float cf0 = __expf(m0r - mn0);
        const float cf1 = __expf(m1r - mn1);
        m0r = mn0; m1r = mn1;

        float ls0 = 0.f, ls1 = 0.f;
#pragma unroll
        for (int nf = 0; nf < 8; nf++) {
            const float p0 = to_tf32(__expf(s[nf][0] - mn0));
            const float p1 = to_tf32(__expf(s[nf][1] - mn0));
            const float p2 = to_tf32(__expf(s[nf][2] - mn1));
            const float p3 = to_tf32(__expf(s[nf][3] - mn1));
            ls0 += p0 + p1; ls1 += p2 + p3;
            const int c2 = nf*8 + 2*cc;
            *(float2*)&Ps[(wm+g)*AP_STR + c2]   = make_float2(p0, p1);
            *(float2*)&Ps[(wm+g+8)*AP_STR + c2] = make_float2(p2, p3);
        }
        ls0 += __shfl_xor_sync(0xffffffffu, ls0, 1);
        ls0 += __shfl_xor_sync(0xffffffffu, ls0, 2);
        ls1 += __shfl_xor_sync(0xffffffffu, ls1, 1);
        ls1 += __shfl_xor_sync(0xffffffffu, ls1, 2);
        l0r = l0r * cf0 + ls0;
        l1r = l1r * cf1 + ls1;

#pragma unroll
        for (int nf = 0; nf < 16; nf++) {
            O[nf][0] *= cf0; O[nf][1] *= cf0;
            O[nf][2] *= cf1; O[nf][3] *= cf1;
        }
        __syncthreads();   // P visible to all lanes

        // ---- O += P @ V : per warp 16x128, K=64 ----
#pragma unroll
        for (int ks = 0; ks < 8; ks++) {
            const int col = ks*8 + cc;
            uint32_t a[4], bb[16][2];
            a[0] = Psu[(wm+g)*AP_STR + col];
            a[1] = Psu[(wm+g+8)*AP_STR + col];
            a[2] = Psu[(wm+g)*AP_STR + col + 4];
            a[3] = Psu[(wm+g+8)*AP_STR + col + 4];
#pragma unroll
            for (int nf = 0; nf < 16; nf++) {
                // B[n=dh][k=kv] = Vs[k][n]
                bb[nf][0] = Vsu[col*AV_STR + nf*8 + g];
                bb[nf][1] = Vsu[(col+4)*AV_STR + nf*8 + g];
            }
#pragma unroll
            for (int nf = 0; nf < 16; nf++)
                MMA_TF32(O[nf], a, bb[nf]);
        }
    }

    // epilogue: normalize, tf32-round, write ctx [B,S,H*DH]
    const float inv0 = 1.0f / l0r;
    const float inv1 = 1.0f / l1r;
    const size_t r0off = ((size_t)(b*SS + qg0)) * DD + h*DHH;
    const size_t r1off = ((size_t)(b*SS + qg8)) * DD + h*DHH;
#pragma unroll
    for (int nf = 0; nf < 16; nf++) {
        const int c2 = nf*8 + 2*cc;
        *(float2*)&CTX[r0off + c2] =
            make_float2(to_tf32(O[nf][0]*inv0), to_tf32(O[nf][1]*inv0));
        *(float2*)&CTX[r1off + c2] =
            make_float2(to_tf32(O[nf][2]*inv1), to_tf32(O[nf][3]*inv1));
    }
}

// ---------------------------------------------------------------------------
// SwiGLU: g = silu(a) * b, tf32-rounded output
// ---------------------------------------------------------------------------
__global__ void __launch_bounds__(256) swiglu_kernel(
    const float* __restrict__ AB, float* __restrict__ G)
{
    const int idx = blockIdx.x * blockDim.x + threadIdx.x;
    const int total4 = ROWS * FFN / 4;
    if (idx >= total4) return;
    const int e = idx * 4;
    const int r = e / FFN;
    const int c = e - r * FFN;
    const float* row = AB + (size_t)r * NFC;
    float4 a = *(const float4*)&row[c];
    float4 bb = *(const float4*)&row[FFN + c];
    float4 o;
    o.x = to_tf32(a.x / (1.0f + expf(-a.x)) * bb.x);
    o.y = to_tf32(a.y / (1.0f + expf(-a.y)) * bb.y);
    o.z = to_tf32(a.z / (1.0f + expf(-a.z)) * bb.z);
    o.w = to_tf32(a.w / (1.0f + expf(-a.w)) * bb.w);
    *(float4*)&G[(size_t)r * FFN + c] = o;
}

// ---------------------------------------------------------------------------
// Launch
// ---------------------------------------------------------------------------
extern "C" void kernel_launch(void* const* d_in, const int* in_sizes, int n_in,
                              void* d_out, int out_size)
{
    const float*         hidden  = (const float*)d_in[0];
    const unsigned char* mask    = (const unsigned char*)d_in[1];
    const int*           pos     = (const int*)d_in[2];
    const float*         ln1_g   = (const float*)d_in[3];
    const float*         ln1_b   = (const float*)d_in[4];
    const float*         Wqkv    = (const float*)d_in[5];
    const float*         Wo      = (const float*)d_in[6];
    const float*         ln2_g   = (const float*)d_in[7];
    const float*         ln2_b   = (const float*)d_in[8];
    const float*         Wfc_in  = (const float*)d_in[9];
    const float*         Wfc_out = (const float*)d_in[10];
    float*               out     = (float*)d_out;

    float *X, *QKV, *Q, *K, *V, *CTX, *H1, *X2, *AB, *G;
    float *WqkvT, *WoT, *WfciT, *WfcoT;
    cudaGetSymbolAddress((void**)&X,     g_X);
    cudaGetSymbolAddress((void**)&QKV,   g_QKV);
    cudaGetSymbolAddress((void**)&Q,     g_Q);
    cudaGetSymbolAddress((void**)&K,     g_K);
    cudaGetSymbolAddress((void**)&V,     g_V);
    cudaGetSymbolAddress((void**)&CTX,   g_CTX);
    cudaGetSymbolAddress((void**)&H1,    g_H1);
    cudaGetSymbolAddress((void**)&X2,    g_X2);
    cudaGetSymbolAddress((void**)&AB,    g_AB);
    cudaGetSymbolAddress((void**)&G,     g_G);
    cudaGetSymbolAddress((void**)&WqkvT, g_WqkvT);
    cudaGetSymbolAddress((void**)&WoT,   g_WoT);
    cudaGetSymbolAddress((void**)&WfciT, g_WfciT);
    cudaGetSymbolAddress((void**)&WfcoT, g_WfcoT);

    cudaFuncSetAttribute(attn_kernel,
                         cudaFuncAttributeMaxDynamicSharedMemorySize,
                         AT_SMEM_BYTES);
    cudaFuncSetAttribute(tgemm<0>,
                         cudaFuncAttributeMaxDynamicSharedMemorySize,
                         GM_SMEM_BYTES);
    cudaFuncSetAttribute(tgemm<1>,
                         cudaFuncAttributeMaxDynamicSharedMemorySize,
                         GM_SMEM_BYTES);

    // 0) transpose + tf32-round weights to [N,K]
    transpose_rna<<<dim3(NQKV/32, DD/32),  dim3(32,8)>>>(Wqkv,    WqkvT, DD,  NQKV);
    transpose_rna<<<dim3(DD/32,   DD/32),  dim3(32,8)>>>(Wo,      WoT,   DD,  DD);
    transpose_rna<<<dim3(NFC/32,  DD/32),  dim3(32,8)>>>(Wfc_in,  WfciT, DD,  NFC);
    transpose_rna<<<dim3(DD/32,   FFN/32), dim3(32,8)>>>(Wfc_out, WfcoT, FFN, DD);

    // 1) LN1
    ln_kernel<<<ROWS, 256>>>(hidden, ln1_g, ln1_b, X);
    // 2) QKV projection
    tgemm<0><<<dim3(NQKV/128, ROWS/128), 256, GM_SMEM_BYTES>>>(
        X, WqkvT, nullptr, QKV, DD, NQKV);
    // 3) RoPE + scatter (tf32-rounded)
    rope_kernel<<<dim3(ROWS, HH), 128>>>(QKV, pos, Q, K, V);
    // 4) attention -> ctx (tensor cores)
    attn_kernel<<<dim3(SS/128, HH, BB), 256, AT_SMEM_BYTES>>>(Q, K, V, mask, CTX);
    // 5) Wo projection + residual
    tgemm<1><<<dim3(DD/128, ROWS/128), 256, GM_SMEM_BYTES>>>(
        CTX, WoT, hidden, H1, DD, DD);
    // 6) LN2
    ln_kernel<<<ROWS, 256>>>(H1, ln2_g, ln2_b, X2);
    // 7) fc_in
    tgemm<0><<<dim3(NFC/128, ROWS/128), 256, GM_SMEM_BYTES>>>(
        X2, WfciT, nullptr, AB, DD, NFC);
    // 8) SwiGLU
    {
        const int total4 = ROWS * FFN / 4;
        swiglu_kernel<<<(total4 + 255)/256, 256>>>(AB, G);
    }
    // 9) fc_out + residual (final output)
    tgemm<1><<<dim3(DD/128, ROWS/128), 256, GM_SMEM_BYTES>>>(
        G, WfcoT, H1, out, FFN, DD);
}

// round 5
// speedup vs baseline: 5.5426x; 1.8634x over previous
#include <cuda_runtime.h>
#include <cuda_fp16.h>
#include <math.h>
#include <stdint.h>

// ---------------------------------------------------------------------------
// Problem constants
// ---------------------------------------------------------------------------
#define BB   2
#define SS   2048
#define DD   2048
#define HH   16
#define DHH  128
#define FFN  5632
#define ROWS (BB*SS)           // 4096
#define NQKV (3*HH*DHH)        // 6144
#define NFC  (2*FFN)           // 11264

// ---------------------------------------------------------------------------
// Scratch (static device globals; allocation is forbidden)
// ---------------------------------------------------------------------------
__device__ __half g_X  [ROWS*DD];    // LN1 out (fp16)
__device__ float  g_QKV[ROWS*NQKV];  // qkv proj (fp32, rope input)
__device__ __half g_Q  [ROWS*DD];    // [B,H,S,DH]
__device__ __half g_K  [ROWS*DD];
__device__ __half g_V  [ROWS*DD];    // [B,H,S,DH]
__device__ __half g_Vt [ROWS*DD];    // [B,H,DH,S]
__device__ __half g_CTX[ROWS*DD];    // [B,S,H*DH]
__device__ float  g_H1 [ROWS*DD];    // residual 1 (fp32)
__device__ __half g_X2 [ROWS*DD];    // LN2 out
__device__ float  g_AB [ROWS*NFC];   // fc_in out (fp32, swiglu input)
__device__ __half g_G  [ROWS*FFN];   // swiglu out
// transposed weights [N,K] K-major, fp16
__device__ __half g_WqkvT [NQKV*DD];
__device__ __half g_WoT   [DD*DD];
__device__ __half g_WfciT [NFC*DD];
__device__ __half g_WfcoT [DD*FFN];

// ---------------------------------------------------------------------------
// Helpers
// ---------------------------------------------------------------------------
__device__ __forceinline__ uint32_t smem_u32(const void* p) {
    uint32_t a;
    asm("{ .reg .u64 t; cvta.to.shared.u64 t, %1; cvt.u32.u64 %0, t; }"
        : "=r"(a) : "l"(p));
    return a;
}

#define CP_ASYNC16(dst, src) \
    asm volatile("cp.async.cg.shared.global [%0], [%1], 16;" \
                 :: "r"(dst), "l"(src))
#define CP_COMMIT() asm volatile("cp.async.commit_group;" ::: "memory")
#define CP_WAIT1()  asm volatile("cp.async.wait_group 1;" ::: "memory")
#define CP_WAIT0()  asm volatile("cp.async.wait_group 0;" ::: "memory")

// fp16 MMA, fp32 accumulate: m16n8k16
#define MMA_F16(d, a, b)                                                   \
    asm volatile(                                                          \
        "mma.sync.aligned.m16n8k16.row.col.f32.f16.f16.f32 "               \
        "{%0,%1,%2,%3}, {%4,%5,%6,%7}, {%8,%9}, {%0,%1,%2,%3};"            \
        : "+f"((d)[0]), "+f"((d)[1]), "+f"((d)[2]), "+f"((d)[3])           \
        : "r"((a)[0]), "r"((a)[1]), "r"((a)[2]), "r"((a)[3]),              \
          "r"((b)[0]), "r"((b)[1]))

// ---------------------------------------------------------------------------
// Weight transpose + fp16 round: W[K,N] f32 -> Wt[N,K] f16
// ---------------------------------------------------------------------------
__global__ void __launch_bounds__(256) transpose_h(
    const float* __restrict__ W, __half* __restrict__ Wt, int K, int N)
{
    __shared__ float t[32][33];
    const int tx = threadIdx.x, ty = threadIdx.y;     // 32 x 8
    const int n0 = blockIdx.x * 32, k0 = blockIdx.y * 32;
#pragma unroll
    for (int j = 0; j < 4; j++)
        t[ty + j*8][tx] = W[(size_t)(k0 + ty + j*8) * N + n0 + tx];
    __syncthreads();
#pragma unroll
    for (int j = 0; j < 4; j++)
        Wt[(size_t)(n0 + ty + j*8) * K + k0 + tx] = __float2half_rn(t[tx][ty + j*8]);
}

// ---------------------------------------------------------------------------
// V transpose: V[bh][S][DH] -> Vt[bh][DH][S]  (fp16)
// ---------------------------------------------------------------------------
__global__ void __launch_bounds__(256) vtrans_kernel(
    const __half* __restrict__ V, __half* __restrict__ Vt)
{
    __shared__ __half t[32][33];
    const int tx = threadIdx.x, ty = threadIdx.y;     // 32 x 8
    const int s0 = blockIdx.x * 32, d0 = blockIdx.y * 32;
    const size_t base = (size_t)blockIdx.z * SS * DHH;
#pragma unroll
    for (int j = 0; j < 4; j++)
        t[ty + j*8][tx] = V[base + (size_t)(s0 + ty + j*8) * DHH + d0 + tx];
    __syncthreads();
#pragma unroll
    for (int j = 0; j < 4; j++)
        Vt[base + (size_t)(d0 + ty + j*8) * SS + s0 + tx] = t[tx][ty + j*8];
}

// ---------------------------------------------------------------------------
// FP16 mma.sync GEMM: C[M,N](f32) = A[M,K](f16) @ Bt[N,K](f16)^T (+R)
// CTA tile 128x128x32, 8 warps (2M x 4N), warp tile 64x32.
// Smem rows: 32 halfs padded to 40 (20 words; g*20+cc distinct mod 32).
// ---------------------------------------------------------------------------
#define AS_W    (128*20)          // words per 128x32 half tile
#define STAGE_W (2*AS_W)
#define GM_SMEM_BYTES (3*STAGE_W*4)   // 61440

template<int EPI>
__global__ void __launch_bounds__(256, 2) tgemm(
    const __half* __restrict__ A, const __half* __restrict__ Bt,
    const float* __restrict__ R, float* __restrict__ C,
    int K, int N)
{
    extern __shared__ uint32_t sm[];

    const int tid  = threadIdx.x;
    const int wid  = tid >> 5;
    const int lane = tid & 31;
    const int g    = lane >> 2;
    const int cc   = lane & 3;
    const int wm   = (wid & 1) * 64;
    const int wn   = (wid >> 1) * 32;

    const int m0 = blockIdx.y * 128;
    const int n0 = blockIdx.x * 128;

    const __half* Ab = A  + (size_t)m0 * K;
    const __half* Bb = Bt + (size_t)n0 * K;

    const int NC = K / 32;

#define LOAD_STAGE(chunk, st) do {                                         \
        const uint32_t asw = smem_u32(sm + (st)*STAGE_W);                  \
        const uint32_t bsw = asw + AS_W*4;                                 \
        const int kt = (chunk) * 32;                                       \
        _Pragma("unroll")                                                  \
        for (int j = 0; j < 2; j++) {                                      \
            const int f = tid + j * 256;                                   \
            const int row = f >> 2, c4 = f & 3;                            \
            CP_ASYNC16(asw + (uint32_t)(row*80 + c4*16),                   \
                       Ab + (size_t)row * K + kt + c4*8);                  \
            CP_ASYNC16(bsw + (uint32_t)(row*80 + c4*16),                   \
                       Bb + (size_t)row * K + kt + c4*8);                  \
        }                                                                  \
        CP_COMMIT();                                                       \
    } while (0)

    float acc[4][4][4];
#pragma unroll
    for (int mf = 0; mf < 4; mf++)
#pragma unroll
        for (int nf = 0; nf < 4; nf++)
#pragma unroll
            for (int q = 0; q < 4; q++) acc[mf][nf][q] = 0.f;

    LOAD_STAGE(0, 0);
    LOAD_STAGE(1, 1);

    for (int i = 0; i < NC; i++) {
        if (i == NC - 1) CP_WAIT0(); else CP_WAIT1();
        __syncthreads();
        if (i + 2 < NC) LOAD_STAGE(i + 2, (i + 2) % 3);

        const uint32_t* Asu = sm + (i % 3) * STAGE_W;
        const uint32_t* Bsu = Asu + AS_W;

#pragma unroll
        for (int ks = 0; ks < 2; ks++) {
            uint32_t a[4][4], b[4][2];
            const int col = ks * 8 + cc;
#pragma unroll
            for (int mf = 0; mf < 4; mf++) {
                const int r0 = wm + mf * 16 + g;
                a[mf][0] = Asu[r0*20 + col];
                a[mf][1] = Asu[(r0+8)*20 + col];
                a[mf][2] = Asu[r0*20 + col + 4];
                a[mf][3] = Asu[(r0+8)*20 + col + 4];
            }
#pragma unroll
            for (int nf = 0; nf < 4; nf++) {
                const int n = wn + nf * 8 + g;
                b[nf][0] = Bsu[n*20 + col];
                b[nf][1] = Bsu[n*20 + col + 4];
            }
#pragma unroll
            for (int mf = 0; mf < 4; mf++)
#pragma unroll
                for (int nf = 0; nf < 4; nf++)
                    MMA_F16(acc[mf][nf], a[mf], b[nf]);
        }
    }
#undef LOAD_STAGE

#pragma unroll
    for (int mf = 0; mf < 4; mf++) {
#pragma unroll
        for (int nf = 0; nf < 4; nf++) {
            const int row = m0 + wm + mf * 16 + g;
            const int col = n0 + wn + nf * 8 + cc * 2;
            const size_t o0 = (size_t)row * N + col;
            const size_t o1 = (size_t)(row + 8) * N + col;
            float2 v0 = { acc[mf][nf][0], acc[mf][nf][1] };
            float2 v1 = { acc[mf][nf][2], acc[mf][nf][3] };
            if (EPI == 1) {
                float2 r0 = *(const float2*)&R[o0];
                float2 r1 = *(const float2*)&R[o1];
                v0.x += r0.x; v0.y += r0.y;
                v1.x += r1.x; v1.y += r1.y;
            }
            *(float2*)&C[o0] = v0;
            *(float2*)&C[o1] = v1;
        }
    }
}

// ---------------------------------------------------------------------------
// LayerNorm: fp32 in, fp16 out
// ---------------------------------------------------------------------------
__global__ void __launch_bounds__(256) ln_kernel(
    const float* __restrict__ X, const float* __restrict__ g,
    const float* __restrict__ b, __half* __restrict__ Y)
{
    const int tid = threadIdx.x;
    const float* x = X + (size_t)blockIdx.x * DD;
    __half* y = Y + (size_t)blockIdx.x * DD;

    float v[8];
    *(float4*)&v[0] = *(const float4*)&x[tid*8];
    *(float4*)&v[4] = *(const float4*)&x[tid*8 + 4];

    float s = 0.f, sq = 0.f;
#pragma unroll
    for (int i = 0; i < 8; i++) { s += v[i]; sq += v[i]*v[i]; }
#pragma unroll
    for (int o = 16; o; o >>= 1) {
        s  += __shfl_xor_sync(0xffffffffu, s,  o);
        sq += __shfl_xor_sync(0xffffffffu, sq, o);
    }
    __shared__ float red[2][8];
    __shared__ float stats[2];
    const int w = tid >> 5, l = tid & 31;
    if (l == 0) { red[0][w] = s; red[1][w] = sq; }
    __syncthreads();
    if (tid == 0) {
        float S = 0.f, SQ = 0.f;
#pragma unroll
        for (int i = 0; i < 8; i++) { S += red[0][i]; SQ += red[1][i]; }
        const float mean = S * (1.0f/DD);
        const float var  = SQ * (1.0f/DD) - mean*mean;
        stats[0] = mean;
        stats[1] = rsqrtf(var + 1e-5f);
    }
    __syncthreads();
    const float mean = stats[0], rstd = stats[1];

    float gv[8], bv[8];
    *(float4*)&gv[0] = *(const float4*)&g[tid*8];
    *(float4*)&gv[4] = *(const float4*)&g[tid*8+4];
    *(float4*)&bv[0] = *(const float4*)&b[tid*8];
    *(float4*)&bv[4] = *(const float4*)&b[tid*8+4];

    __half2 h[4];
#pragma unroll
    for (int i = 0; i < 4; i++) {
        const float a0 = (v[2*i]   - mean) * rstd * gv[2*i]   + bv[2*i];
        const float a1 = (v[2*i+1] - mean) * rstd * gv[2*i+1] + bv[2*i+1];
        h[i] = __floats2half2_rn(a0, a1);
    }
    *(uint4*)&y[tid*8] = *(uint4*)h;
}

// ---------------------------------------------------------------------------
// RoPE + scatter: QKV f32 [B,S,H,3*DH] -> Q/K/V f16 [B,H,S,DH]
// ---------------------------------------------------------------------------
__global__ void __launch_bounds__(128) rope_kernel(
    const float* __restrict__ QKV, const int* __restrict__ pos_ids,
    __half* __restrict__ Q, __half* __restrict__ K, __half* __restrict__ V)
{
    const int bs = blockIdx.x;
    const int h  = blockIdx.y;
    const int d  = threadIdx.x;
    const int pos = pos_ids[bs];

    const float* row = QKV + (size_t)bs * NQKV + h * (3*DHH);
    const float q = row[d];
    const float k = row[DHH + d];
    const float v = row[2*DHH + d];

    const int j = d & 63;
    const float inv = 1.0f / powf(10000.0f, (float)(2*j) * (1.0f/128.0f));
    const float fr = (float)pos * inv;
    const float sn = sinf(fr), cs = cosf(fr);

    float qo, ko;
    if (d < 64) {
        qo = q * cs - row[d + 64] * sn;
        ko = k * cs - row[DHH + d + 64] * sn;
    } else {
        qo = q * cs + row[d - 64] * sn;
        ko = k * cs + row[DHH + d - 64] * sn;
    }
    const int b = bs >> 11, s = bs & 2047;
    const size_t o = (((size_t)(b*HH + h)) * SS + s) * DHH + d;
    Q[o] = __float2half_rn(qo);
    K[o] = __float2half_rn(ko);
    V[o] = __float2half_rn(v);
}

// ---------------------------------------------------------------------------
// Flash attention, fp16 mma.sync m16n8k16.
// Q tile 128 rows (8 warps x 16 rows), K/V tiles 64 cols, online softmax.
// Smem word strides: Q/K 68, Vt/P 36 (g*stride+cc distinct mod 32).
// ---------------------------------------------------------------------------
#define AQ_WS 68
#define AK_WS 68
#define AV_WS 36
#define AP_WS 36
#define AT_SMEM_WORDS (128*AQ_WS + 64*AK_WS + 128*AV_WS + 128*AP_WS)
#define AT_SMEM_BYTES (AT_SMEM_WORDS*4)   // 89088

__global__ void __launch_bounds__(256) attn_kernel(
    const __half* __restrict__ Q, const __half* __restrict__ K,
    const __half* __restrict__ Vt, const unsigned char* __restrict__ mask,
    __half* __restrict__ CTX)
{
    extern __shared__ uint32_t smu[];
    uint32_t* Qs  = smu;                    // [128][AQ_WS]  (m, dh halfs)
    uint32_t* Ks  = Qs + 128*AQ_WS;         // [64][AK_WS]   (kv, dh halfs)
    uint32_t* Vts = Ks + 64*AK_WS;          // [128][AV_WS]  (dh, kv halfs)
    uint32_t* Ps  = Vts + 128*AV_WS;        // [128][AP_WS]  (m, kv halfs)

    const int tid  = threadIdx.x;
    const int wid  = tid >> 5;
    const int lane = tid & 31;
    const int g    = lane >> 2;
    const int cc   = lane & 3;
    const int wm   = wid * 16;

    const int qt = blockIdx.x, h = blockIdx.y, b = blockIdx.z;
    const size_t headoff = ((size_t)(b*HH + h)) * SS * DHH;
    const __half* Qg  = Q  + headoff + (size_t)qt * 128 * DHH;
    const __half* Vtg = Vt + headoff;    // [DH][S]

    // load Q tile 128x128 halfs
#pragma unroll
    for (int j = 0; j < 8; j++) {
        const int f = tid + j * 256;
        const int r = f >> 4, c8 = f & 15;
        *(uint4*)(Qs + r*AQ_WS + c8*4) = *(const uint4*)(Qg + r*DHH + c8*8);
    }

    float m0r = -1e30f, m1r = -1e30f, l0r = 0.f, l1r = 0.f;
    float O[16][4];
#pragma unroll
    for (int nf = 0; nf < 16; nf++)
#pragma unroll
        for (int q = 0; q < 4; q++) O[nf][q] = 0.f;

    const float scale = 0.08838834764831845f;   // 1/sqrt(128)
    const unsigned char* mrow = mask + (size_t)b * SS * SS;
    const int qg0 = qt * 128 + wm + g;
    const int qg8 = qg0 + 8;

    for (int kt = 0; kt < SS; kt += 64) {
        __syncthreads();
        const __half* Kg = K + headoff + (size_t)kt * DHH;
#pragma unroll
        for (int j = 0; j < 4; j++) {
            const int f = tid + j * 256;
            {   // K tile: 64 rows x 128 halfs
                const int r = f >> 4, c8 = f & 15;
                *(uint4*)(Ks + r*AK_WS + c8*4) =
                    *(const uint4*)(Kg + r*DHH + c8*8);
            }
            {   // Vt tile: 128 rows (dh) x 64 halfs (kv)
                const int r = f >> 3, c8 = f & 7;
                *(uint4*)(Vts + r*AV_WS + c8*4) =
                    *(const uint4*)(Vtg + (size_t)r*SS + kt + c8*8);
            }
        }
        // prefetch mask bytes (rows qg0/qg8, cols kt+nf*8+2cc, 2 bytes)
        unsigned short mRa[8], mRb[8];
        {
            const unsigned char* mpA = mrow + (size_t)qg0 * SS + kt + 2*cc;
            const unsigned char* mpB = mrow + (size_t)qg8 * SS + kt + 2*cc;
#pragma unroll
            for (int nf = 0; nf < 8; nf++) {
                mRa[nf] = *(const unsigned short*)(mpA + nf*8);
                mRb[nf] = *(const unsigned short*)(mpB + nf*8);
            }
        }
        __syncthreads();

        // ---- S = Q @ K^T : per warp 16x64, k=dh=128 (8 MMA k-steps) ----
        float s[8][4];
#pragma unroll
        for (int nf = 0; nf < 8; nf++)
#pragma unroll
            for (int q = 0; q < 4; q++) s[nf][q] = 0.f;

#pragma unroll
        for (int ks = 0; ks < 8; ks++) {
            const int col = ks*8 + cc;
            uint32_t a[4], bb[8][2];
            a[0] = Qs[(wm+g)*AQ_WS + col];
            a[1] = Qs[(wm+g+8)*AQ_WS + col];
            a[2] = Qs[(wm+g)*AQ_WS + col + 4];
            a[3] = Qs[(wm+g+8)*AQ_WS + col + 4];
#pragma unroll
            for (int nf = 0; nf < 8; nf++) {
                bb[nf][0] = Ks[(nf*8+g)*AK_WS + col];
                bb[nf][1] = Ks[(nf*8+g)*AK_WS + col + 4];
            }
#pragma unroll
            for (int nf = 0; nf < 8; nf++)
                MMA_F16(s[nf], a, bb[nf]);
        }

        // ---- online softmax ----
        float rmax0 = -1e30f, rmax1 = -1e30f;
#pragma unroll
        for (int nf = 0; nf < 8; nf++) {
            float s0 = s[nf][0]*scale, s1 = s[nf][1]*scale;
            float s2 = s[nf][2]*scale, s3 = s[nf][3]*scale;
            if (mRa[nf] & 0x00ffu) s0 = -10000.f;
            if (mRa[nf] & 0xff00u) s1 = -10000.f;
            if (mRb[nf] & 0x00ffu) s2 = -10000.f;
            if (mRb[nf] & 0xff00u) s3 = -10000.f;
            s[nf][0] = s0; s[nf][1] = s1; s[nf][2] = s2; s[nf][3] = s3;
            rmax0 = fmaxf(rmax0, fmaxf(s0, s1));
            rmax1 = fmaxf(rmax1, fmaxf(s2, s3));
        }
        rmax0 = fmaxf(rmax0, __shfl_xor_sync(0xffffffffu, rmax0, 1));
        rmax0 = fmaxf(rmax0, __shfl_xor_sync(0xffffffffu, rmax0, 2));
        rmax1 = fmaxf(rmax1, __shfl_xor_sync(0xffffffffu, rmax1, 1));
        rmax1 = fmaxf(rmax1, __shfl_xor_sync(0xffffffffu, rmax1, 2));

        const float mn0 = fmaxf(m0r, rmax0);
        const float mn1 = fmaxf(m1r, rmax1);
        const float cf0 = __expf(m0r - mn0);
        const float cf1 = __expf(m1r - mn1);
        m0r = mn0; m1r = mn1;

        float ls0 = 0.f, ls1 = 0.f;
#pragma unroll
        for (int nf = 0; nf < 8; nf++) {
            const float p0 = __expf(s[nf][0] - mn0);
            const float p1 = __expf(s[nf][1] - mn0);
            const float p2 = __expf(s[nf][2] - mn1);
            const float p3 = __expf(s[nf][3] - mn1);
            ls0 += p0 + p1; ls1 += p2 + p3;
            const __half2 h01 = __floats2half2_rn(p0, p1);
            const __half2 h23 = __floats2half2_rn(p2, p3);
            Ps[(wm+g)*AP_WS + nf*4 + cc]   = *(const uint32_t*)&h01;
            Ps[(wm+g+8)*AP_WS + nf*4 + cc] = *(const uint32_t*)&h23;
        }
        ls0 += __shfl_xor_sync(0xffffffffu, ls0, 1);
        ls0 += __shfl_xor_sync(0xffffffffu, ls0, 2);
        ls1 += __shfl_xor_sync(0xffffffffu, ls1, 1);
        ls1 += __shfl_xor_sync(0xffffffffu, ls1, 2);
        l0r = l0r * cf0 + ls0;
        l1r = l1r * cf1 + ls1;

#pragma unroll
        for (int nf = 0; nf < 16; nf++) {
            O[nf][0] *= cf0; O[nf][1] *= cf0;
            O[nf][2] *= cf1; O[nf][3] *= cf1;
        }
        __syncthreads();   // P visible to all lanes

        // ---- O += P @ V : per warp 16x128, k=kv=64 (4 MMA k-steps) ----
#pragma unroll
        for (int ks = 0; ks < 4; ks++) {
            const int col = ks*8 + cc;
            uint32_t a[4], bb[16][2];
            a[0] = Ps[(wm+g)*AP_WS + col];
            a[1] = Ps[(wm+g+8)*AP_WS + col];
            a[2] = Ps[(wm+g)*AP_WS + col + 4];
            a[3] = Ps[(wm+g+8)*AP_WS + col + 4];
#pragma unroll
            for (int nf = 0; nf < 16; nf++) {
                bb[nf][0] = Vts[(nf*8+g)*AV_WS + col];
                bb[nf][1] = Vts[(nf*8+g)*AV_WS + col + 4];
            }
#pragma unroll
            for (int nf = 0; nf < 16; nf++)
                MMA_F16(O[nf], a, bb[nf]);
        }
    }

    // epilogue: normalize, write ctx fp16 [B,S,H*DH]
    const float inv0 = 1.0f / l0r;
    const float inv1 = 1.0f / l1r;
    __half* C0 = CTX + ((size_t)(b*SS + qg0)) * DD + h*DHH;
    __half* C1 = CTX + ((size_t)(b*SS + qg8)) * DD + h*DHH;
#pragma unroll
    for (int nf = 0; nf < 16; nf++) {
        const int c2 = nf*8 + 2*cc;
        const __half2 h0 = __floats2half2_rn(O[nf][0]*inv0, O[nf][1]*inv0);
        const __half2 h1 = __floats2half2_rn(O[nf][2]*inv1, O[nf][3]*inv1);
        *(uint32_t*)(C0 + c2) = *(const uint32_t*)&h0;
        *(uint32_t*)(C1 + c2) = *(const uint32_t*)&h1;
    }
}

// ---------------------------------------------------------------------------
// SwiGLU: f32 in, f16 out
// ---------------------------------------------------------------------------
__global__ void __launch_bounds__(256) swiglu_kernel(
    const float* __restrict__ AB, __half* __restrict__ G)
{
    const int idx = blockIdx.x * blockDim.x + threadIdx.x;
    const int total4 = ROWS * FFN / 4;
    if (idx >= total4) return;
    const int e = idx * 4;
    const int r = e / FFN;
    const int c = e - r * FFN;
    const float* row = AB + (size_t)r * NFC;
    float4 a = *(const float4*)&row[c];
    float4 bb = *(const float4*)&row[FFN + c];
    const float o0 = a.x / (1.0f + __expf(-a.x)) * bb.x;
    const float o1 = a.y / (1.0f + __expf(-a.y)) * bb.y;
    const float o2 = a.z / (1.0f + __expf(-a.z)) * bb.z;
    const float o3 = a.w / (1.0f + __expf(-a.w)) * bb.w;
    __half2 h0 = __floats2half2_rn(o0, o1);
    __half2 h1 = __floats2half2_rn(o2, o3);
    uint2 pk = { *(const uint32_t*)&h0, *(const uint32_t*)&h1 };
    *(uint2*)&G[(size_t)r * FFN + c] = pk;
}

// ---------------------------------------------------------------------------
// Launch
// ---------------------------------------------------------------------------
extern "C" void kernel_launch(void* const* d_in, const int* in_sizes, int n_in,
                              void* d_out, int out_size)
{
    const float*         hidden  = (const float*)d_in[0];
    const unsigned char* mask    = (const unsigned char*)d_in[1];
    const int*           pos     = (const int*)d_in[2];
    const float*         ln1_g   = (const float*)d_in[3];
    const float*         ln1_b   = (const float*)d_in[4];
    const float*         Wqkv    = (const float*)d_in[5];
    const float*         Wo      = (const float*)d_in[6];
    const float*         ln2_g   = (const float*)d_in[7];
    const float*         ln2_b   = (const float*)d_in[8];
    const float*         Wfc_in  = (const float*)d_in[9];
    const float*         Wfc_out = (const float*)d_in[10];
    float*               out     = (float*)d_out;

    __half *X, *Q, *K, *V, *Vt, *CTX, *X2, *G;
    __half *WqkvT, *WoT, *WfciT, *WfcoT;
    float *QKV, *H1, *AB;
    cudaGetSymbolAddress((void**)&X,     g_X);
    cudaGetSymbolAddress((void**)&QKV,   g_QKV);
    cudaGetSymbolAddress((void**)&Q,     g_Q);
    cudaGetSymbolAddress((void**)&K,     g_K);
    cudaGetSymbolAddress((void**)&V,     g_V);
    cudaGetSymbolAddress((void**)&Vt,    g_Vt);
    cudaGetSymbolAddress((void**)&CTX,   g_CTX);
    cudaGetSymbolAddress((void**)&H1,    g_H1);
    cudaGetSymbolAddress((void**)&X2,    g_X2);
    cudaGetSymbolAddress((void**)&AB,    g_AB);
    cudaGetSymbolAddress((void**)&G,     g_G);
    cudaGetSymbolAddress((void**)&WqkvT, g_WqkvT);
    cudaGetSymbolAddress((void**)&WoT,   g_WoT);
    cudaGetSymbolAddress((void**)&WfciT, g_WfciT);
    cudaGetSymbolAddress((void**)&WfcoT, g_WfcoT);

    cudaFuncSetAttribute(attn_kernel,
                         cudaFuncAttributeMaxDynamicSharedMemorySize,
                         AT_SMEM_BYTES);
    cudaFuncSetAttribute(tgemm<0>,
                         cudaFuncAttributeMaxDynamicSharedMemorySize,
                         GM_SMEM_BYTES);
    cudaFuncSetAttribute(tgemm<1>,
                         cudaFuncAttributeMaxDynamicSharedMemorySize,
                         GM_SMEM_BYTES);

    // 0) transpose + fp16 weights -> [N,K]
    transpose_h<<<dim3(NQKV/32, DD/32),  dim3(32,8)>>>(Wqkv,    WqkvT, DD,  NQKV);
    transpose_h<<<dim3(DD/32,   DD/32),  dim3(32,8)>>>(Wo,      WoT,   DD,  DD);
    transpose_h<<<dim3(NFC/32,  DD/32),  dim3(32,8)>>>(Wfc_in,  WfciT, DD,  NFC);
    transpose_h<<<dim3(DD/32,   FFN/32), dim3(32,8)>>>(Wfc_out, WfcoT, FFN, DD);

    // 1) LN1 (fp16 out)
    ln_kernel<<<ROWS, 256>>>(hidden, ln1_g, ln1_b, X);
    // 2) QKV projection
    tgemm<0><<<dim3(NQKV/128, ROWS/128), 256, GM_SMEM_BYTES>>>(
        X, WqkvT, nullptr, QKV, DD, NQKV);
    // 3) RoPE + scatter (fp16 out)
    rope_kernel<<<dim3(ROWS, HH), 128>>>(QKV, pos, Q, K, V);
    // 3b) V transpose -> [B,H,DH,S]
    vtrans_kernel<<<dim3(SS/32, DHH/32, BB*HH), dim3(32,8)>>>(V, Vt);
    // 4) attention -> ctx (fp16)
    attn_kernel<<<dim3(SS/128, HH, BB), 256, AT_SMEM_BYTES>>>(Q, K, Vt, mask, CTX);
    // 5) Wo projection + residual
    tgemm<1><<<dim3(DD/128, ROWS/128), 256, GM_SMEM_BYTES>>>(
        CTX, WoT, hidden, H1, DD, DD);
    // 6) LN2 (fp16 out)
    ln_kernel<<<ROWS, 256>>>(H1, ln2_g, ln2_b, X2);
    // 7) fc_in
    tgemm<0><<<dim3(NFC/128, ROWS/128), 256, GM_SMEM_BYTES>>>(
        X2, WfciT, nullptr, AB, DD, NFC);
    // 8) SwiGLU (fp16 out)
    {
        const int total4 = ROWS * FFN / 4;
        swiglu_kernel<<<(total4 + 255)/256, 256>>>(AB, G);
    }
    // 9) fc_out + residual (final output, f32)
    tgemm<1><<<dim3(DD/128, ROWS/128), 256, GM_SMEM_BYTES>>>(
        G, WfcoT, H1, out, FFN, DD);
}

// round 6
// speedup vs baseline: 5.6081x; 1.0118x over previous
#include <cuda_runtime.h>
#include <cuda_fp16.h>
#include <math.h>
#include <stdint.h>

// ---------------------------------------------------------------------------
// Problem constants
// ---------------------------------------------------------------------------
#define BB   2
#define SS   2048
#define DD   2048
#define HH   16
#define DHH  128
#define FFN  5632
#define ROWS (BB*SS)           // 4096
#define NQKV (3*HH*DHH)        // 6144
#define NFC  (2*FFN)           // 11264

// ---------------------------------------------------------------------------
// Scratch
// ---------------------------------------------------------------------------
__device__ __half g_X  [ROWS*DD];    // LN1 out
__device__ __half g_QKV[ROWS*NQKV];  // qkv proj (fp16)
__device__ __half g_Q  [ROWS*DD];    // [B,H,S,DH]
__device__ __half g_K  [ROWS*DD];
__device__ __half g_V  [ROWS*DD];    // [B,H,S,DH]
__device__ __half g_Vt [ROWS*DD];    // [B,H,DH,S]
__device__ __half g_CTX[ROWS*DD];    // [B,S,H*DH]
__device__ float  g_H1 [ROWS*DD];    // residual 1 (fp32)
__device__ __half g_X2 [ROWS*DD];    // LN2 out
__device__ __half g_AB [ROWS*NFC];   // fc_in out (fp16)
__device__ __half g_G  [ROWS*FFN];   // swiglu out
// transposed weights [N,K] K-major, fp16
__device__ __half g_WqkvT [NQKV*DD];
__device__ __half g_WoT   [DD*DD];
__device__ __half g_WfciT [NFC*DD];
__device__ __half g_WfcoT [DD*FFN];

// ---------------------------------------------------------------------------
// Helpers
// ---------------------------------------------------------------------------
__device__ __forceinline__ uint32_t smem_u32(const void* p) {
    uint32_t a;
    asm("{ .reg .u64 t; cvta.to.shared.u64 t, %1; cvt.u32.u64 %0, t; }"
        : "=r"(a) : "l"(p));
    return a;
}

#define CP_ASYNC16(dst, src) \
    asm volatile("cp.async.cg.shared.global [%0], [%1], 16;" \
                 :: "r"(dst), "l"(src))
#define CP_COMMIT() asm volatile("cp.async.commit_group;" ::: "memory")
#define CP_WAIT1()  asm volatile("cp.async.wait_group 1;" ::: "memory")
#define CP_WAIT0()  asm volatile("cp.async.wait_group 0;" ::: "memory")

#define MMA_F16(d, a, b)                                                   \
    asm volatile(                                                          \
        "mma.sync.aligned.m16n8k16.row.col.f32.f16.f16.f32 "               \
        "{%0,%1,%2,%3}, {%4,%5,%6,%7}, {%8,%9}, {%0,%1,%2,%3};"            \
        : "+f"((d)[0]), "+f"((d)[1]), "+f"((d)[2]), "+f"((d)[3])           \
        : "r"((a)[0]), "r"((a)[1]), "r"((a)[2]), "r"((a)[3]),              \
          "r"((b)[0]), "r"((b)[1]))

#define LDSM_X4(r0, r1, r2, r3, addr)                                      \
    asm volatile("ldmatrix.sync.aligned.m8n8.x4.shared.b16 "               \
                 "{%0,%1,%2,%3}, [%4];"                                    \
                 : "=r"(r0), "=r"(r1), "=r"(r2), "=r"(r3) : "r"(addr))

#define LDSM_X2(r0, r1, addr)                                              \
    asm volatile("ldmatrix.sync.aligned.m8n8.x2.shared.b16 "               \
                 "{%0,%1}, [%2];"                                          \
                 : "=r"(r0), "=r"(r1) : "r"(addr))

// ---------------------------------------------------------------------------
// Weight transpose + fp16 round: W[K,N] f32 -> Wt[N,K] f16
// ---------------------------------------------------------------------------
__global__ void __launch_bounds__(256) transpose_h(
    const float* __restrict__ W, __half* __restrict__ Wt, int K, int N)
{
    __shared__ float t[32][33];
    const int tx = threadIdx.x, ty = threadIdx.y;
    const int n0 = blockIdx.x * 32, k0 = blockIdx.y * 32;
#pragma unroll
    for (int j = 0; j < 4; j++)
        t[ty + j*8][tx] = W[(size_t)(k0 + ty + j*8) * N + n0 + tx];
    __syncthreads();
#pragma unroll
    for (int j = 0; j < 4; j++)
        Wt[(size_t)(n0 + ty + j*8) * K + k0 + tx] = __float2half_rn(t[tx][ty + j*8]);
}

// ---------------------------------------------------------------------------
// V transpose: V[bh][S][DH] -> Vt[bh][DH][S]  (fp16)
// ---------------------------------------------------------------------------
__global__ void __launch_bounds__(256) vtrans_kernel(
    const __half* __restrict__ V, __half* __restrict__ Vt)
{
    __shared__ __half t[32][33];
    const int tx = threadIdx.x, ty = threadIdx.y;
    const int s0 = blockIdx.x * 32, d0 = blockIdx.y * 32;
    const size_t base = (size_t)blockIdx.z * SS * DHH;
#pragma unroll
    for (int j = 0; j < 4; j++)
        t[ty + j*8][tx] = V[base + (size_t)(s0 + ty + j*8) * DHH + d0 + tx];
    __syncthreads();
#pragma unroll
    for (int j = 0; j < 4; j++)
        Vt[base + (size_t)(d0 + ty + j*8) * SS + s0 + tx] = t[tx][ty + j*8];
}

// ---------------------------------------------------------------------------
// FP16 mma.sync GEMM with ldmatrix fragment loads.
// CTA tile 128x128x32, 8 warps (2M x 4N), warp tile 64x32.
// Smem rows: 32 halfs padded to 80 bytes (granule stride 5 -> ldmatrix
// conflict-free: (5r+c) mod 8 is a permutation).
// EPI: 0 = plain store, 1 = +residual. OUTH: 1 = fp16 output.
// ---------------------------------------------------------------------------
#define TILE_BYTES 10240              // 128 rows * 80 B
#define STAGE_BYTES (2*TILE_BYTES)
#define GM_SMEM_BYTES (3*STAGE_BYTES) // 61440

template<int EPI, int OUTH>
__global__ void __launch_bounds__(256, 2) tgemm(
    const __half* __restrict__ A, const __half* __restrict__ Bt,
    const float* __restrict__ R, void* __restrict__ Cv,
    int K, int N)
{
    extern __shared__ char smc[];
    const uint32_t smb = smem_u32(smc);

    const int tid  = threadIdx.x;
    const int wid  = tid >> 5;
    const int lane = tid & 31;
    const int g    = lane >> 2;
    const int cc   = lane & 3;
    const int wm   = (wid & 1) * 64;
    const int wn   = (wid >> 1) * 32;

    const int m0 = blockIdx.y * 128;
    const int n0 = blockIdx.x * 128;

    const __half* Ab = A  + (size_t)m0 * K;
    const __half* Bb = Bt + (size_t)n0 * K;

    const int NC = K / 32;

    // ldmatrix per-lane base offsets (within a tile)
    const uint32_t aoff = (uint32_t)(wm + (lane & 15)) * 80 + (lane >> 4) * 16;
    const uint32_t boff = (uint32_t)(wn + (lane & 7)) * 80 + ((lane >> 3) & 1) * 16;

#define LOAD_STAGE(chunk, st) do {                                         \
        const uint32_t asw = smb + (st)*STAGE_BYTES;                       \
        const uint32_t bsw = asw + TILE_BYTES;                             \
        const int kt = (chunk) * 32;                                       \
        _Pragma("unroll")                                                  \
        for (int j = 0; j < 2; j++) {                                      \
            const int f = tid + j * 256;                                   \
            const int row = f >> 2, c4 = f & 3;                            \
            CP_ASYNC16(asw + (uint32_t)(row*80 + c4*16),                   \
                       Ab + (size_t)row * K + kt + c4*8);                  \
            CP_ASYNC16(bsw + (uint32_t)(row*80 + c4*16),                   \
                       Bb + (size_t)row * K + kt + c4*8);                  \
        }                                                                  \
        CP_COMMIT();                                                       \
    } while (0)

    float acc[4][4][4];
#pragma unroll
    for (int mf = 0; mf < 4; mf++)
#pragma unroll
        for (int nf = 0; nf < 4; nf++)
#pragma unroll
            for (int q = 0; q < 4; q++) acc[mf][nf][q] = 0.f;

    LOAD_STAGE(0, 0);
    LOAD_STAGE(1, 1);

    for (int i = 0; i < NC; i++) {
        if (i == NC - 1) CP_WAIT0(); else CP_WAIT1();
        __syncthreads();
        if (i + 2 < NC) LOAD_STAGE(i + 2, (i + 2) % 3);

        const uint32_t abase = smb + (i % 3) * STAGE_BYTES;
        const uint32_t bbase = abase + TILE_BYTES;

#pragma unroll
        for (int ks = 0; ks < 2; ks++) {
            uint32_t a[4][4], b[4][2];
#pragma unroll
            for (int mf = 0; mf < 4; mf++)
                LDSM_X4(a[mf][0], a[mf][1], a[mf][2], a[mf][3],
                        abase + aoff + mf*1280 + ks*32);
#pragma unroll
            for (int nf = 0; nf < 4; nf++)
                LDSM_X2(b[nf][0], b[nf][1],
                        bbase + boff + nf*640 + ks*32);
#pragma unroll
            for (int mf = 0; mf < 4; mf++)
#pragma unroll
                for (int nf = 0; nf < 4; nf++)
                    MMA_F16(acc[mf][nf], a[mf], b[nf]);
        }
    }
#undef LOAD_STAGE

#pragma unroll
    for (int mf = 0; mf < 4; mf++) {
#pragma unroll
        for (int nf = 0; nf < 4; nf++) {
            const int row = m0 + wm + mf * 16 + g;
            const int col = n0 + wn + nf * 8 + cc * 2;
            const size_t o0 = (size_t)row * N + col;
            const size_t o1 = (size_t)(row + 8) * N + col;
            float2 v0 = { acc[mf][nf][0], acc[mf][nf][1] };
            float2 v1 = { acc[mf][nf][2], acc[mf][nf][3] };
            if (EPI == 1) {
                float2 r0 = *(const float2*)&R[o0];
                float2 r1 = *(const float2*)&R[o1];
                v0.x += r0.x; v0.y += r0.y;
                v1.x += r1.x; v1.y += r1.y;
            }
            if (OUTH == 1) {
                __half* C = (__half*)Cv;
                const __half2 h0 = __floats2half2_rn(v0.x, v0.y);
                const __half2 h1 = __floats2half2_rn(v1.x, v1.y);
                *(uint32_t*)&C[o0] = *(const uint32_t*)&h0;
                *(uint32_t*)&C[o1] = *(const uint32_t*)&h1;
            } else {
                float* C = (float*)Cv;
                *(float2*)&C[o0] = v0;
                *(float2*)&C[o1] = v1;
            }
        }
    }
}

// ---------------------------------------------------------------------------
// LayerNorm: fp32 in, fp16 out
// ---------------------------------------------------------------------------
__global__ void __launch_bounds__(256) ln_kernel(
    const float* __restrict__ X, const float* __restrict__ g,
    const float* __restrict__ b, __half* __restrict__ Y)
{
    const int tid = threadIdx.x;
    const float* x = X + (size_t)blockIdx.x * DD;
    __half* y = Y + (size_t)blockIdx.x * DD;

    float v[8];
    *(float4*)&v[0] = *(const float4*)&x[tid*8];
    *(float4*)&v[4] = *(const float4*)&x[tid*8 + 4];

    float s = 0.f, sq = 0.f;
#pragma unroll
    for (int i = 0; i < 8; i++) { s += v[i]; sq += v[i]*v[i]; }
#pragma unroll
    for (int o = 16; o; o >>= 1) {
        s  += __shfl_xor_sync(0xffffffffu, s,  o);
        sq += __shfl_xor_sync(0xffffffffu, sq, o);
    }
    __shared__ float red[2][8];
    __shared__ float stats[2];
    const int w = tid >> 5, l = tid & 31;
    if (l == 0) { red[0][w] = s; red[1][w] = sq; }
    __syncthreads();
    if (tid == 0) {
        float S = 0.f, SQ = 0.f;
#pragma unroll
        for (int i = 0; i < 8; i++) { S += red[0][i]; SQ += red[1][i]; }
        const float mean = S * (1.0f/DD);
        const float var  = SQ * (1.0f/DD) - mean*mean;
        stats[0] = mean;
        stats[1] = rsqrtf(var + 1e-5f);
    }
    __syncthreads();
    const float mean = stats[0], rstd = stats[1];

    float gv[8], bv[8];
    *(float4*)&gv[0] = *(const float4*)&g[tid*8];
    *(float4*)&gv[4] = *(const float4*)&g[tid*8+4];
    *(float4*)&bv[0] = *(const float4*)&b[tid*8];
    *(float4*)&bv[4] = *(const float4*)&b[tid*8+4];

    __half2 h[4];
#pragma unroll
    for (int i = 0; i < 4; i++) {
        const float a0 = (v[2*i]   - mean) * rstd * gv[2*i]   + bv[2*i];
        const float a1 = (v[2*i+1] - mean) * rstd * gv[2*i+1] + bv[2*i+1];
        h[i] = __floats2half2_rn(a0, a1);
    }
    *(uint4*)&y[tid*8] = *(uint4*)h;
}

// ---------------------------------------------------------------------------
// RoPE + scatter: QKV f16 [B,S,H,3*DH] -> Q/K/V f16 [B,H,S,DH]
// ---------------------------------------------------------------------------
__global__ void __launch_bounds__(128) rope_kernel(
    const __half* __restrict__ QKV, const int* __restrict__ pos_ids,
    __half* __restrict__ Q, __half* __restrict__ K, __half* __restrict__ V)
{
    const int bs = blockIdx.x;
    const int h  = blockIdx.y;
    const int d  = threadIdx.x;
    const int pos = pos_ids[bs];

    const __half* row = QKV + (size_t)bs * NQKV + h * (3*DHH);
    const float q = __half2float(row[d]);
    const float k = __half2float(row[DHH + d]);
    const __half v = row[2*DHH + d];

    const int j = d & 63;
    const float inv = 1.0f / powf(10000.0f, (float)(2*j) * (1.0f/128.0f));
    const float fr = (float)pos * inv;
    const float sn = sinf(fr), cs = cosf(fr);

    float qo, ko;
    if (d < 64) {
        qo = q * cs - __half2float(row[d + 64]) * sn;
        ko = k * cs - __half2float(row[DHH + d + 64]) * sn;
    } else {
        qo = q * cs + __half2float(row[d - 64]) * sn;
        ko = k * cs + __half2float(row[DHH + d - 64]) * sn;
    }
    const int b = bs >> 11, s = bs & 2047;
    const size_t o = (((size_t)(b*HH + h)) * SS + s) * DHH + d;
    Q[o] = __float2half_rn(qo);
    K[o] = __float2half_rn(ko);
    V[o] = v;
}

// ---------------------------------------------------------------------------
// Flash attention, fp16 mma.sync + ldmatrix, Q fragments hoisted to regs.
// Q tile 128 rows (8 warps x 16), K/V tiles 64 cols, online softmax.
// Word strides: Q/K 68 (272B, 17 granules), Vt/P 36 (144B, 9 granules)
// -> (17r+c) & (9r+c) mod 8 are permutations -> ldmatrix conflict-free.
// ---------------------------------------------------------------------------
#define AQ_WS 68
#define AK_WS 68
#define AV_WS 36
#define AP_WS 36
#define AT_SMEM_WORDS (128*AQ_WS + 64*AK_WS + 128*AV_WS + 128*AP_WS)
#define AT_SMEM_BYTES (AT_SMEM_WORDS*4)   // 89088

__global__ void __launch_bounds__(256) attn_kernel(
    const __half* __restrict__ Q, const __half* __restrict__ K,
    const __half* __restrict__ Vt, const unsigned char* __restrict__ mask,
    __half* __restrict__ CTX)
{
    extern __shared__ uint32_t smu[];
    uint32_t* Qs  = smu;                    // [128][AQ_WS]
    uint32_t* Ks  = Qs + 128*AQ_WS;         // [64][AK_WS]
    uint32_t* Vts = Ks + 64*AK_WS;          // [128][AV_WS]
    uint32_t* Ps  = Vts + 128*AV_WS;        // [128][AP_WS]

    const int tid  = threadIdx.x;
    const int wid  = tid >> 5;
    const int lane = tid & 31;
    const int g    = lane >> 2;
    const int cc   = lane & 3;
    const int wm   = wid * 16;

    const int qt = blockIdx.x, h = blockIdx.y, b = blockIdx.z;
    const size_t headoff = ((size_t)(b*HH + h)) * SS * DHH;
    const __half* Qg  = Q  + headoff + (size_t)qt * 128 * DHH;
    const __half* Vtg = Vt + headoff;    // [DH][S]

    // load Q tile 128x128 halfs
#pragma unroll
    for (int j = 0; j < 8; j++) {
        const int f = tid + j * 256;
        const int r = f >> 4, c8 = f & 15;
        *(uint4*)(Qs + r*AQ_WS + c8*4) = *(const uint4*)(Qg + r*DHH + c8*8);
    }
    __syncthreads();

    // hoist Q fragments: qf[ks][0..3] for ks = 0..7 (dh chunks of 16)
    uint32_t qf[8][4];
    {
        const uint32_t qaddr = smem_u32(Qs)
            + (uint32_t)(wm + (lane & 15)) * (AQ_WS*4) + (lane >> 4) * 16;
#pragma unroll
        for (int ks = 0; ks < 8; ks++)
            LDSM_X4(qf[ks][0], qf[ks][1], qf[ks][2], qf[ks][3],
                    qaddr + ks*32);
    }

    const uint32_t kaddr = smem_u32(Ks)
        + (uint32_t)(lane & 7) * (AK_WS*4) + ((lane >> 3) & 1) * 16;
    const uint32_t paddr = smem_u32(Ps)
        + (uint32_t)(wm + (lane & 15)) * (AP_WS*4) + (lane >> 4) * 16;
    const uint32_t vaddr = smem_u32(Vts)
        + (uint32_t)(lane & 7) * (AV_WS*4) + ((lane >> 3) & 1) * 16;

    float m0r = -1e30f, m1r = -1e30f, l0r = 0.f, l1r = 0.f;
    float O[16][4];
#pragma unroll
    for (int nf = 0; nf < 16; nf++)
#pragma unroll
        for (int q = 0; q < 4; q++) O[nf][q] = 0.f;

    const float scale = 0.08838834764831845f;
    const unsigned char* mrow = mask + (size_t)b * SS * SS;
    const int qg0 = qt * 128 + wm + g;
    const int qg8 = qg0 + 8;

    for (int kt = 0; kt < SS; kt += 64) {
        __syncthreads();
        const __half* Kg = K + headoff + (size_t)kt * DHH;
#pragma unroll
        for (int j = 0; j < 4; j++) {
            const int f = tid + j * 256;
            {   // K tile: 64 rows x 128 halfs
                const int r = f >> 4, c8 = f & 15;
                *(uint4*)(Ks + r*AK_WS + c8*4) =
                    *(const uint4*)(Kg + r*DHH + c8*8);
            }
            {   // Vt tile: 128 rows (dh) x 64 halfs (kv)
                const int r = f >> 3, c8 = f & 7;
                *(uint4*)(Vts + r*AV_WS + c8*4) =
                    *(const uint4*)(Vtg + (size_t)r*SS + kt + c8*8);
            }
        }
        unsigned short mRa[8], mRb[8];
        {
            const unsigned char* mpA = mrow + (size_t)qg0 * SS + kt + 2*cc;
            const unsigned char* mpB = mrow + (size_t)qg8 * SS + kt + 2*cc;
#pragma unroll
            for (int nf = 0; nf < 8; nf++) {
                mRa[nf] = *(const unsigned short*)(mpA + nf*8);
                mRb[nf] = *(const unsigned short*)(mpB + nf*8);
            }
        }
        __syncthreads();

        // ---- S = Q @ K^T : per warp 16x64, 8 k-steps ----
        float s[8][4];
#pragma unroll
        for (int nf = 0; nf < 8; nf++)
#pragma unroll
            for (int q = 0; q < 4; q++) s[nf][q] = 0.f;

#pragma unroll
        for (int ks = 0; ks < 8; ks++) {
            uint32_t bb[8][2];
#pragma unroll
            for (int nf = 0; nf < 8; nf++)
                LDSM_X2(bb[nf][0], bb[nf][1],
                        kaddr + nf*8*(AK_WS*4) + ks*32);
#pragma unroll
            for (int nf = 0; nf < 8; nf++)
                MMA_F16(s[nf], qf[ks], bb[nf]);
        }

        // ---- online softmax ----
        float rmax0 = -1e30f, rmax1 = -1e30f;
#pragma unroll
        for (int nf = 0; nf < 8; nf++) {
            float s0 = s[nf][0]*scale, s1 = s[nf][1]*scale;
            float s2 = s[nf][2]*scale, s3 = s[nf][3]*scale;
            if (mRa[nf] & 0x00ffu) s0 = -10000.f;
            if (mRa[nf] & 0xff00u) s1 = -10000.f;
            if (mRb[nf] & 0x00ffu) s2 = -10000.f;
            if (mRb[nf] & 0xff00u) s3 = -10000.f;
            s[nf][0] = s0; s[nf][1] = s1; s[nf][2] = s2; s[nf][3] = s3;
            rmax0 = fmaxf(rmax0, fmaxf(s0, s1));
            rmax1 = fmaxf(rmax1, fmaxf(s2, s3));
        }
        rmax0 = fmaxf(rmax0, __shfl_xor_sync(0xffffffffu, rmax0, 1));
        rmax0 = fmaxf(rmax0, __shfl_xor_sync(0xffffffffu, rmax0, 2));
        rmax1 = fmaxf(rmax1, __shfl_xor_sync(0xffffffffu, rmax1, 1));
        rmax1 = fmaxf(rmax1, __shfl_xor_sync(0xffffffffu, rmax1, 2));

        const float mn0 = fmaxf(m0r, rmax0);
        const float mn1 = fmaxf(m1r, rmax1);
        const float cf0 = __expf(m0r - mn0);
        const float cf1 = __expf(m1r - mn1);
        m0r = mn0; m1r = mn1;

        float ls0 = 0.f, ls1 = 0.f;
#pragma unroll
        for (int nf = 0; nf < 8; nf++) {
            const float p0 = __expf(s[nf][0] - mn0);
            const float p1 = __expf(s[nf][1] - mn0);
            const float p2 = __expf(s[nf][2] - mn1);
            const float p3 = __expf(s[nf][3] - mn1);
            ls0 += p0 + p1; ls1 += p2 + p3;
            const __half2 h01 = __floats2half2_rn(p0, p1);
            const __half2 h23 = __floats2half2_rn(p2, p3);
            Ps[(wm+g)*AP_WS + nf*4 + cc]   = *(const uint32_t*)&h01;
            Ps[(wm+g+8)*AP_WS + nf*4 + cc] = *(const uint32_t*)&h23;
        }
        ls0 += __shfl_xor_sync(0xffffffffu, ls0, 1);
        ls0 += __shfl_xor_sync(0xffffffffu, ls0, 2);
        ls1 += __shfl_xor_sync(0xffffffffu, ls1, 1);
        ls1 += __shfl_xor_sync(0xffffffffu, ls1, 2);
        l0r = l0r * cf0 + ls0;
        l1r = l1r * cf1 + ls1;

#pragma unroll
        for (int nf = 0; nf < 16; nf++) {
            O[nf][0] *= cf0; O[nf][1] *= cf0;
            O[nf][2] *= cf1; O[nf][3] *= cf1;
        }
        __syncthreads();   // P visible to all lanes

        // ---- O += P @ V : per warp 16x128, 4 k-steps ----
#pragma unroll
        for (int ks = 0; ks < 4; ks++) {
            uint32_t a[4], bb[16][2];
            LDSM_X4(a[0], a[1], a[2], a[3], paddr + ks*32);
#pragma unroll
            for (int nf = 0; nf < 16; nf++)
                LDSM_X2(bb[nf][0], bb[nf][1],
                        vaddr + nf*8*(AV_WS*4) + ks*32);
#pragma unroll
            for (int nf = 0; nf < 16; nf++)
                MMA_F16(O[nf], a, bb[nf]);
        }
    }

    // epilogue
    const float inv0 = 1.0f / l0r;
    const float inv1 = 1.0f / l1r;
    __half* C0 = CTX + ((size_t)(b*SS + qg0)) * DD + h*DHH;
    __half* C1 = CTX + ((size_t)(b*SS + qg8)) * DD + h*DHH;
#pragma unroll
    for (int nf = 0; nf < 16; nf++) {
        const int c2 = nf*8 + 2*cc;
        const __half2 h0 = __floats2half2_rn(O[nf][0]*inv0, O[nf][1]*inv0);
        const __half2 h1 = __floats2half2_rn(O[nf][2]*inv1, O[nf][3]*inv1);
        *(uint32_t*)(C0 + c2) = *(const uint32_t*)&h0;
        *(uint32_t*)(C1 + c2) = *(const uint32_t*)&h1;
    }
}

// ---------------------------------------------------------------------------
// SwiGLU: f16 in, f16 out
// ---------------------------------------------------------------------------
__global__ void __launch_bounds__(256) swiglu_kernel(
    const __half* __restrict__ AB, __half* __restrict__ G)
{
    const int idx = blockIdx.x * blockDim.x + threadIdx.x;
    const int total4 = ROWS * FFN / 4;
    if (idx >= total4) return;
    const int e = idx * 4;
    const int r = e / FFN;
    const int c = e - r * FFN;
    const __half* row = AB + (size_t)r * NFC;
    __half2 a01 = *(const __half2*)&row[c];
    __half2 a23 = *(const __half2*)&row[c + 2];
    __half2 b01 = *(const __half2*)&row[FFN + c];
    __half2 b23 = *(const __half2*)&row[FFN + c + 2];
    const float a0 = __half2float(a01.x), a1 = __half2float(a01.y);
    const float a2 = __half2float(a23.x), a3 = __half2float(a23.y);
    const float o0 = a0 / (1.0f + __expf(-a0)) * __half2float(b01.x);
    const float o1 = a1 / (1.0f + __expf(-a1)) * __half2float(b01.y);
    const float o2 = a2 / (1.0f + __expf(-a2)) * __half2float(b23.x);
    const float o3 = a3 / (1.0f + __expf(-a3)) * __half2float(b23.y);
    __half2 h0 = __floats2half2_rn(o0, o1);
    __half2 h1 = __floats2half2_rn(o2, o3);
    uint2 pk = { *(const uint32_t*)&h0, *(const uint32_t*)&h1 };
    *(uint2*)&G[(size_t)r * FFN + c] = pk;
}

// ---------------------------------------------------------------------------
// Launch
// ---------------------------------------------------------------------------
extern "C" void kernel_launch(void* const* d_in, const int* in_sizes, int n_in,
                              void* d_out, int out_size)
{
    const float*         hidden  = (const float*)d_in[0];
    const unsigned char* mask    = (const unsigned char*)d_in[1];
    const int*           pos     = (const int*)d_in[2];
    const float*         ln1_g   = (const float*)d_in[3];
    const float*         ln1_b   = (const float*)d_in[4];
    const float*         Wqkv    = (const float*)d_in[5];
    const float*         Wo      = (const float*)d_in[6];
    const float*         ln2_g   = (const float*)d_in[7];
    const float*         ln2_b   = (const float*)d_in[8];
    const float*         Wfc_in  = (const float*)d_in[9];
    const float*         Wfc_out = (const float*)d_in[10];
    float*               out     = (float*)d_out;

    __half *X, *QKV, *Q, *K, *V, *Vt, *CTX, *X2, *AB, *G;
    __half *WqkvT, *WoT, *WfciT, *WfcoT;
    float *H1;
    cudaGetSymbolAddress((void**)&X,     g_X);
    cudaGetSymbolAddress((void**)&QKV,   g_QKV);
    cudaGetSymbolAddress((void**)&Q,     g_Q);
    cudaGetSymbolAddress((void**)&K,     g_K);
    cudaGetSymbolAddress((void**)&V,     g_V);
    cudaGetSymbolAddress((void**)&Vt,    g_Vt);
    cudaGetSymbolAddress((void**)&CTX,   g_CTX);
    cudaGetSymbolAddress((void**)&H1,    g_H1);
    cudaGetSymbolAddress((void**)&X2,    g_X2);
    cudaGetSymbolAddress((void**)&AB,    g_AB);
    cudaGetSymbolAddress((void**)&G,     g_G);
    cudaGetSymbolAddress((void**)&WqkvT, g_WqkvT);
    cudaGetSymbolAddress((void**)&WoT,   g_WoT);
    cudaGetSymbolAddress((void**)&WfciT, g_WfciT);
    cudaGetSymbolAddress((void**)&WfcoT, g_WfcoT);

    cudaFuncSetAttribute(attn_kernel,
                         cudaFuncAttributeMaxDynamicSharedMemorySize,
                         AT_SMEM_BYTES);
    cudaFuncSetAttribute((tgemm<0,1>),
                         cudaFuncAttributeMaxDynamicSharedMemorySize,
                         GM_SMEM_BYTES);
    cudaFuncSetAttribute((tgemm<1,0>),
                         cudaFuncAttributeMaxDynamicSharedMemorySize,
                         GM_SMEM_BYTES);

    // 0) transpose + fp16 weights -> [N,K]
    transpose_h<<<dim3(NQKV/32, DD/32),  dim3(32,8)>>>(Wqkv,    WqkvT, DD,  NQKV);
    transpose_h<<<dim3(DD/32,   DD/32),  dim3(32,8)>>>(Wo,      WoT,   DD,  DD);
    transpose_h<<<dim3(NFC/32,  DD/32),  dim3(32,8)>>>(Wfc_in,  WfciT, DD,  NFC);
    transpose_h<<<dim3(DD/32,   FFN/32), dim3(32,8)>>>(Wfc_out, WfcoT, FFN, DD);

    // 1) LN1 (fp16 out)
    ln_kernel<<<ROWS, 256>>>(hidden, ln1_g, ln1_b, X);
    // 2) QKV projection (fp16 out)
    tgemm<0,1><<<dim3(NQKV/128, ROWS/128), 256, GM_SMEM_BYTES>>>(
        X, WqkvT, nullptr, QKV, DD, NQKV);
    // 3) RoPE + scatter
    rope_kernel<<<dim3(ROWS, HH), 128>>>(QKV, pos, Q, K, V);
    // 3b) V transpose -> [B,H,DH,S]
    vtrans_kernel<<<dim3(SS/32, DHH/32, BB*HH), dim3(32,8)>>>(V, Vt);
    // 4) attention -> ctx (fp16)
    attn_kernel<<<dim3(SS/128, HH, BB), 256, AT_SMEM_BYTES>>>(Q, K, Vt, mask, CTX);
    // 5) Wo projection + residual (f32 out)
    tgemm<1,0><<<dim3(DD/128, ROWS/128), 256, GM_SMEM_BYTES>>>(
        CTX, WoT, hidden, H1, DD, DD);
    // 6) LN2 (fp16 out)
    ln_kernel<<<ROWS, 256>>>(H1, ln2_g, ln2_b, X2);
    // 7) fc_in (fp16 out)
    tgemm<0,1><<<dim3(NFC/128, ROWS/128), 256, GM_SMEM_BYTES>>>(
        X2, WfciT, nullptr, AB, DD, NFC);
    // 8) SwiGLU (fp16 out)
    {
        const int total4 = ROWS * FFN / 4;
        swiglu_kernel<<<(total4 + 255)/256, 256>>>(AB, G);
    }
    // 9) fc_out + residual (final output, f32)
    tgemm<1,0><<<dim3(DD/128, ROWS/128), 256, GM_SMEM_BYTES>>>(
        G, WfcoT, H1, out, FFN, DD);
}

// round 7
// speedup vs baseline: 5.9692x; 1.0644x over previous
#include <cuda_runtime.h>
#include <cuda_fp16.h>
#include <math.h>
#include <stdint.h>

// ---------------------------------------------------------------------------
// Problem constants
// ---------------------------------------------------------------------------
#define BB   2
#define SS   2048
#define DD   2048
#define HH   16
#define DHH  128
#define FFN  5632
#define ROWS (BB*SS)           // 4096
#define NQKV (3*HH*DHH)        // 6144
#define NFC  (2*FFN)           // 11264

// ---------------------------------------------------------------------------
// Scratch
// ---------------------------------------------------------------------------
__device__ __half g_X  [ROWS*DD];    // LN1 out
__device__ __half g_QKV[ROWS*NQKV];  // qkv proj (fp16)
__device__ __half g_Q  [ROWS*DD];    // [B,H,S,DH]
__device__ __half g_K  [ROWS*DD];
__device__ __half g_V  [ROWS*DD];    // [B,H,S,DH]
__device__ __half g_CTX[ROWS*DD];    // [B,S,H*DH]
__device__ float  g_H1 [ROWS*DD];    // residual 1 (fp32)
__device__ __half g_X2 [ROWS*DD];    // LN2 out
__device__ __half g_AB [ROWS*NFC];   // fc_in out (fp16)
__device__ __half g_G  [ROWS*FFN];   // swiglu out
// transposed weights [N,K] K-major, fp16
__device__ __half g_WqkvT [NQKV*DD];
__device__ __half g_WoT   [DD*DD];
__device__ __half g_WfciT [NFC*DD];
__device__ __half g_WfcoT [DD*FFN];

// ---------------------------------------------------------------------------
// Helpers
// ---------------------------------------------------------------------------
__device__ __forceinline__ uint32_t smem_u32(const void* p) {
    uint32_t a;
    asm("{ .reg .u64 t; cvta.to.shared.u64 t, %1; cvt.u32.u64 %0, t; }"
        : "=r"(a) : "l"(p));
    return a;
}

#define CP_ASYNC16(dst, src) \
    asm volatile("cp.async.cg.shared.global [%0], [%1], 16;" \
                 :: "r"(dst), "l"(src))
#define CP_COMMIT() asm volatile("cp.async.commit_group;" ::: "memory")
#define CP_WAIT2()  asm volatile("cp.async.wait_group 2;" ::: "memory")
#define CP_WAIT1()  asm volatile("cp.async.wait_group 1;" ::: "memory")
#define CP_WAIT0()  asm volatile("cp.async.wait_group 0;" ::: "memory")

#define MMA_F16(d, a, b)                                                   \
    asm volatile(                                                          \
        "mma.sync.aligned.m16n8k16.row.col.f32.f16.f16.f32 "               \
        "{%0,%1,%2,%3}, {%4,%5,%6,%7}, {%8,%9}, {%0,%1,%2,%3};"            \
        : "+f"((d)[0]), "+f"((d)[1]), "+f"((d)[2]), "+f"((d)[3])           \
        : "r"((a)[0]), "r"((a)[1]), "r"((a)[2]), "r"((a)[3]),              \
          "r"((b)[0]), "r"((b)[1]))

#define LDSM_X4(r0, r1, r2, r3, addr)                                      \
    asm volatile("ldmatrix.sync.aligned.m8n8.x4.shared.b16 "               \
                 "{%0,%1,%2,%3}, [%4];"                                    \
                 : "=r"(r0), "=r"(r1), "=r"(r2), "=r"(r3) : "r"(addr))

#define LDSM_X2(r0, r1, addr)                                              \
    asm volatile("ldmatrix.sync.aligned.m8n8.x2.shared.b16 "               \
                 "{%0,%1}, [%2];"                                          \
                 : "=r"(r0), "=r"(r1) : "r"(addr))

#define LDSM_X2T(r0, r1, addr)                                             \
    asm volatile("ldmatrix.sync.aligned.m8n8.x2.trans.shared.b16 "         \
                 "{%0,%1}, [%2];"                                          \
                 : "=r"(r0), "=r"(r1) : "r"(addr))

// ---------------------------------------------------------------------------
// Weight transpose + fp16 round: W[K,N] f32 -> Wt[N,K] f16
// ---------------------------------------------------------------------------
__global__ void __launch_bounds__(256) transpose_h(
    const float* __restrict__ W, __half* __restrict__ Wt, int K, int N)
{
    __shared__ float t[32][33];
    const int tx = threadIdx.x, ty = threadIdx.y;
    const int n0 = blockIdx.x * 32, k0 = blockIdx.y * 32;
#pragma unroll
    for (int j = 0; j < 4; j++)
        t[ty + j*8][tx] = W[(size_t)(k0 + ty + j*8) * N + n0 + tx];
    __syncthreads();
#pragma unroll
    for (int j = 0; j < 4; j++)
        Wt[(size_t)(n0 + ty + j*8) * K + k0 + tx] = __float2half_rn(t[tx][ty + j*8]);
}

// ---------------------------------------------------------------------------
// FP16 mma.sync GEMM, ldmatrix fragments, 4-stage cp.async pipeline.
// CTA tile 128x128x32, 8 warps (2M x 4N), warp tile 64x32.
// Smem rows: 32 halfs padded to 80 B (granule stride 5 -> conflict-free).
// ---------------------------------------------------------------------------
#define TILE_BYTES 10240              // 128 rows * 80 B
#define STAGE_BYTES (2*TILE_BYTES)
#define GM_SMEM_BYTES (4*STAGE_BYTES) // 81920

template<int EPI, int OUTH>
__global__ void __launch_bounds__(256, 2) tgemm(
    const __half* __restrict__ A, const __half* __restrict__ Bt,
    const float* __restrict__ R, void* __restrict__ Cv,
    int K, int N)
{
    extern __shared__ char smc[];
    const uint32_t smb = smem_u32(smc);

    const int tid  = threadIdx.x;
    const int wid  = tid >> 5;
    const int lane = tid & 31;
    const int g    = lane >> 2;
    const int cc   = lane & 3;
    const int wm   = (wid & 1) * 64;
    const int wn   = (wid >> 1) * 32;

    const int m0 = blockIdx.y * 128;
    const int n0 = blockIdx.x * 128;

    const __half* Ab = A  + (size_t)m0 * K;
    const __half* Bb = Bt + (size_t)n0 * K;

    const int NC = K / 32;

    const uint32_t aoff = (uint32_t)(wm + (lane & 15)) * 80 + (lane >> 4) * 16;
    const uint32_t boff = (uint32_t)(wn + (lane & 7)) * 80 + ((lane >> 3) & 1) * 16;

#define LOAD_STAGE(chunk, st) do {                                         \
        const uint32_t asw = smb + (st)*STAGE_BYTES;                       \
        const uint32_t bsw = asw + TILE_BYTES;                             \
        const int kt = (chunk) * 32;                                       \
        _Pragma("unroll")                                                  \
        for (int j = 0; j < 2; j++) {                                      \
            const int f = tid + j * 256;                                   \
            const int row = f >> 2, c4 = f & 3;                            \
            CP_ASYNC16(asw + (uint32_t)(row*80 + c4*16),                   \
                       Ab + (size_t)row * K + kt + c4*8);                  \
            CP_ASYNC16(bsw + (uint32_t)(row*80 + c4*16),                   \
                       Bb + (size_t)row * K + kt + c4*8);                  \
        }                                                                  \
        CP_COMMIT();                                                       \
    } while (0)

    float acc[4][4][4];
#pragma unroll
    for (int mf = 0; mf < 4; mf++)
#pragma unroll
        for (int nf = 0; nf < 4; nf++)
#pragma unroll
            for (int q = 0; q < 4; q++) acc[mf][nf][q] = 0.f;

    LOAD_STAGE(0, 0);
    LOAD_STAGE(1, 1);
    LOAD_STAGE(2, 2);

    for (int i = 0; i < NC; i++) {
        if (i < NC - 2)       CP_WAIT2();
        else if (i == NC - 2) CP_WAIT1();
        else                  CP_WAIT0();
        __syncthreads();
        if (i + 3 < NC) LOAD_STAGE(i + 3, (i + 3) & 3);

        const uint32_t abase = smb + (i & 3) * STAGE_BYTES;
        const uint32_t bbase = abase + TILE_BYTES;

#pragma unroll
        for (int ks = 0; ks < 2; ks++) {
            uint32_t a[4][4], b[4][2];
#pragma unroll
            for (int mf = 0; mf < 4; mf++)
                LDSM_X4(a[mf][0], a[mf][1], a[mf][2], a[mf][3],
                        abase + aoff + mf*1280 + ks*32);
#pragma unroll
            for (int nf = 0; nf < 4; nf++)
                LDSM_X2(b[nf][0], b[nf][1],
                        bbase + boff + nf*640 + ks*32);
#pragma unroll
            for (int mf = 0; mf < 4; mf++)
#pragma unroll
                for (int nf = 0; nf < 4; nf++)
                    MMA_F16(acc[mf][nf], a[mf], b[nf]);
        }
    }
#undef LOAD_STAGE

#pragma unroll
    for (int mf = 0; mf < 4; mf++) {
#pragma unroll
        for (int nf = 0; nf < 4; nf++) {
            const int row = m0 + wm + mf * 16 + g;
            const int col = n0 + wn + nf * 8 + cc * 2;
            const size_t o0 = (size_t)row * N + col;
            const size_t o1 = (size_t)(row + 8) * N + col;
            float2 v0 = { acc[mf][nf][0], acc[mf][nf][1] };
            float2 v1 = { acc[mf][nf][2], acc[mf][nf][3] };
            if (EPI == 1) {
                float2 r0 = *(const float2*)&R[o0];
                float2 r1 = *(const float2*)&R[o1];
                v0.x += r0.x; v0.y += r0.y;
                v1.x += r1.x; v1.y += r1.y;
            }
            if (OUTH == 1) {
                __half* C = (__half*)Cv;
                const __half2 h0 = __floats2half2_rn(v0.x, v0.y);
                const __half2 h1 = __floats2half2_rn(v1.x, v1.y);
                *(uint32_t*)&C[o0] = *(const uint32_t*)&h0;
                *(uint32_t*)&C[o1] = *(const uint32_t*)&h1;
            } else {
                float* C = (float*)Cv;
                *(float2*)&C[o0] = v0;
                *(float2*)&C[o1] = v1;
            }
        }
    }
}

// ---------------------------------------------------------------------------
// LayerNorm: fp32 in, fp16 out
// ---------------------------------------------------------------------------
__global__ void __launch_bounds__(256) ln_kernel(
    const float* __restrict__ X, const float* __restrict__ g,
    const float* __restrict__ b, __half* __restrict__ Y)
{
    const int tid = threadIdx.x;
    const float* x = X + (size_t)blockIdx.x * DD;
    __half* y = Y + (size_t)blockIdx.x * DD;

    float v[8];
    *(float4*)&v[0] = *(const float4*)&x[tid*8];
    *(float4*)&v[4] = *(const float4*)&x[tid*8 + 4];

    float s = 0.f, sq = 0.f;
#pragma unroll
    for (int i = 0; i < 8; i++) { s += v[i]; sq += v[i]*v[i]; }
#pragma unroll
    for (int o = 16; o; o >>= 1) {
        s  += __shfl_xor_sync(0xffffffffu, s,  o);
        sq += __shfl_xor_sync(0xffffffffu, sq, o);
    }
    __shared__ float red[2][8];
    __shared__ float stats[2];
    const int w = tid >> 5, l = tid & 31;
    if (l == 0) { red[0][w] = s; red[1][w] = sq; }
    __syncthreads();
    if (tid == 0) {
        float S = 0.f, SQ = 0.f;
#pragma unroll
        for (int i = 0; i < 8; i++) { S += red[0][i]; SQ += red[1][i]; }
        const float mean = S * (1.0f/DD);
        const float var  = SQ * (1.0f/DD) - mean*mean;
        stats[0] = mean;
        stats[1] = rsqrtf(var + 1e-5f);
    }
    __syncthreads();
    const float mean = stats[0], rstd = stats[1];

    float gv[8], bv[8];
    *(float4*)&gv[0] = *(const float4*)&g[tid*8];
    *(float4*)&gv[4] = *(const float4*)&g[tid*8+4];
    *(float4*)&bv[0] = *(const float4*)&b[tid*8];
    *(float4*)&bv[4] = *(const float4*)&b[tid*8+4];

    __half2 h[4];
#pragma unroll
    for (int i = 0; i < 4; i++) {
        const float a0 = (v[2*i]   - mean) * rstd * gv[2*i]   + bv[2*i];
        const float a1 = (v[2*i+1] - mean) * rstd * gv[2*i+1] + bv[2*i+1];
        h[i] = __floats2half2_rn(a0, a1);
    }
    *(uint4*)&y[tid*8] = *(uint4*)h;
}

// ---------------------------------------------------------------------------
// RoPE + scatter: QKV f16 [B,S,H,3*DH] -> Q/K/V f16 [B,H,S,DH]
// ---------------------------------------------------------------------------
__global__ void __launch_bounds__(128) rope_kernel(
    const __half* __restrict__ QKV, const int* __restrict__ pos_ids,
    __half* __restrict__ Q, __half* __restrict__ K, __half* __restrict__ V)
{
    const int bs = blockIdx.x;
    const int h  = blockIdx.y;
    const int d  = threadIdx.x;
    const int pos = pos_ids[bs];

    const __half* row = QKV + (size_t)bs * NQKV + h * (3*DHH);
    const float q = __half2float(row[d]);
    const float k = __half2float(row[DHH + d]);
    const __half v = row[2*DHH + d];

    const int j = d & 63;
    const float inv = 1.0f / powf(10000.0f, (float)(2*j) * (1.0f/128.0f));
    const float fr = (float)pos * inv;
    const float sn = sinf(fr), cs = cosf(fr);

    float qo, ko;
    if (d < 64) {
        qo = q * cs - __half2float(row[d + 64]) * sn;
        ko = k * cs - __half2float(row[DHH + d + 64]) * sn;
    } else {
        qo = q * cs + __half2float(row[d - 64]) * sn;
        ko = k * cs + __half2float(row[DHH + d - 64]) * sn;
    }
    const int b = bs >> 11, s = bs & 2047;
    const size_t o = (((size_t)(b*HH + h)) * SS + s) * DHH + d;
    Q[o] = __float2half_rn(qo);
    K[o] = __float2half_rn(ko);
    V[o] = v;
}

// ---------------------------------------------------------------------------
// Flash attention: fp16 mma + ldmatrix, cp.async double-buffered K/V tiles,
// V consumed in [kv][dh] layout via ldmatrix.trans (no pre-transpose).
// Q fragments hoisted to registers; Q smem region reused for P.
// smem words: QP 8704 | K 2x4352 | V 2x4352  = 26112 (104448 B)
// ---------------------------------------------------------------------------
#define AT_SMEM_BYTES (26112*4)

__global__ void __launch_bounds__(256) attn_kernel(
    const __half* __restrict__ Q, const __half* __restrict__ K,
    const __half* __restrict__ V, const unsigned char* __restrict__ mask,
    __half* __restrict__ CTX)
{
    extern __shared__ uint32_t smu[];
    uint32_t* QPs = smu;                 // Q: [128][68]w, then P: [128][36]w
    const uint32_t smb = smem_u32(smu);
    const uint32_t kB0 = smb + 8704*4;
    const uint32_t vB0 = smb + 17408*4;
#define KBUF(bf) (kB0 + (bf)*17408)
#define VBUF(bf) (vB0 + (bf)*17408)

    const int tid  = threadIdx.x;
    const int lane = tid & 31;
    const int wid  = tid >> 5;
    const int g    = lane >> 2;
    const int cc   = lane & 3;
    const int wm   = wid * 16;

    const int qt = blockIdx.x, h = blockIdx.y, b = blockIdx.z;
    const size_t headoff = ((size_t)(b*HH + h)) * SS * DHH;
    const __half* Qg    = Q + headoff + (size_t)qt * 128 * DHH;
    const __half* Kbase = K + headoff;
    const __half* Vbase = V + headoff;

    // async load Q tile (group), then KV tiles 0 and 1 (groups)
#pragma unroll
    for (int j = 0; j < 8; j++) {
        const int f = tid + j * 256;
        const int r = f >> 4, c = f & 15;
        CP_ASYNC16(smb + (uint32_t)(r*272 + c*16), Qg + r*DHH + c*8);
    }
    CP_COMMIT();

#define LOAD_KV(t, bf) do {                                                \
        const __half* Kg_ = Kbase + (size_t)(t) * 64 * DHH;                \
        const __half* Vg_ = Vbase + (size_t)(t) * 64 * DHH;                \
        _Pragma("unroll")                                                  \
        for (int j = 0; j < 4; j++) {                                      \
            const int f = tid + j * 256;                                   \
            const int r = f >> 4, c = f & 15;                              \
            CP_ASYNC16(KBUF(bf) + (uint32_t)(r*272 + c*16),                \
                       Kg_ + r*DHH + c*8);                                 \
            CP_ASYNC16(VBUF(bf) + (uint32_t)(r*272 + c*16),                \
                       Vg_ + r*DHH + c*8);                                 \
        }                                                                  \
        CP_COMMIT();                                                       \
    } while (0)

    LOAD_KV(0, 0);
    LOAD_KV(1, 1);

    CP_WAIT1();            // Q + KV0 ready
    __syncthreads();

    // hoist Q fragments (dh chunks of 16)
    uint32_t qf[8][4];
    {
        const uint32_t qaddr = smb + (uint32_t)(wm + (lane & 15)) * 272
                             + (lane >> 4) * 16;
#pragma unroll
        for (int ks = 0; ks < 8; ks++)
            LDSM_X4(qf[ks][0], qf[ks][1], qf[ks][2], qf[ks][3], qaddr + ks*32);
    }
    __syncthreads();       // Q region now reusable as P

    const uint32_t kaddrL = (uint32_t)(lane & 7) * 272 + ((lane >> 3) & 1) * 16;
    const uint32_t vaddrL = (uint32_t)(lane & 15) * 272;
    const uint32_t paddr  = smb + (uint32_t)(wm + (lane & 15)) * 144
                          + (lane >> 4) * 16;

    float m0r = -1e30f, m1r = -1e30f, l0r = 0.f, l1r = 0.f;
    float O[16][4];
#pragma unroll
    for (int nf = 0; nf < 16; nf++)
#pragma unroll
        for (int q = 0; q < 4; q++) O[nf][q] = 0.f;

    const float scale = 0.08838834764831845f;
    const unsigned char* mrow = mask + (size_t)b * SS * SS;
    const int qg0 = qt * 128 + wm + g;
    const int qg8 = qg0 + 8;

    for (int t = 0; t < 32; t++) {
        const int bf = t & 1;
        const int kt = t * 64;

        // mask bytes for this tile
        unsigned short mRa[8], mRb[8];
        {
            const unsigned char* mpA = mrow + (size_t)qg0 * SS + kt + 2*cc;
            const unsigned char* mpB = mrow + (size_t)qg8 * SS + kt + 2*cc;
#pragma unroll
            for (int nf = 0; nf < 8; nf++) {
                mRa[nf] = *(const unsigned short*)(mpA + nf*8);
                mRb[nf] = *(const unsigned short*)(mpB + nf*8);
            }
        }

        // ---- S = Q @ K^T : per warp 16x64, 8 k-steps ----
        float s[8][4];
#pragma unroll
        for (int nf = 0; nf < 8; nf++)
#pragma unroll
            for (int q = 0; q < 4; q++) s[nf][q] = 0.f;

        const uint32_t kb = KBUF(bf) + kaddrL;
#pragma unroll
        for (int ks = 0; ks < 8; ks++) {
            uint32_t bb[8][2];
#pragma unroll
            for (int nf = 0; nf < 8; nf++)
                LDSM_X2(bb[nf][0], bb[nf][1], kb + nf*2176 + ks*32);
#pragma unroll
            for (int nf = 0; nf < 8; nf++)
                MMA_F16(s[nf], qf[ks], bb[nf]);
        }

        // ---- online softmax ----
        float rmax0 = -1e30f, rmax1 = -1e30f;
#pragma unroll
        for (int nf = 0; nf < 8; nf++) {
            float s0 = s[nf][0]*scale, s1 = s[nf][1]*scale;
            float s2 = s[nf][2]*scale, s3 = s[nf][3]*scale;
            if (mRa[nf] & 0x00ffu) s0 = -10000.f;
            if (mRa[nf] & 0xff00u) s1 = -10000.f;
            if (mRb[nf] & 0x00ffu) s2 = -10000.f;
            if (mRb[nf] & 0xff00u) s3 = -10000.f;
            s[nf][0] = s0; s[nf][1] = s1; s[nf][2] = s2; s[nf][3] = s3;
            rmax0 = fmaxf(rmax0, fmaxf(s0, s1));
            rmax1 = fmaxf(rmax1, fmaxf(s2, s3));
        }
        rmax0 = fmaxf(rmax0, __shfl_xor_sync(0xffffffffu, rmax0, 1));
        rmax0 = fmaxf(rmax0, __shfl_xor_sync(0xffffffffu, rmax0, 2));
        rmax1 = fmaxf(rmax1, __shfl_xor_sync(0xffffffffu, rmax1, 1));
        rmax1 = fmaxf(rmax1, __shfl_xor_sync(0xffffffffu, rmax1, 2));

        const float mn0 = fmaxf(m0r, rmax0);
        const float mn1 = fmaxf(m1r, rmax1);
        const float cf0 = __expf(m0r - mn0);
        const float cf1 = __expf(m1r - mn1);
        m0r = mn0; m1r = mn1;

        float ls0 = 0.f, ls1 = 0.f;
#pragma unroll
        for (int nf = 0; nf < 8; nf++) {
            const float p0 = __expf(s[nf][0] - mn0);
            const float p1 = __expf(s[nf][1] - mn0);
            const float p2 = __expf(s[nf][2] - mn1);
            const float p3 = __expf(s[nf][3] - mn1);
            ls0 += p0 + p1; ls1 += p2 + p3;
            const __half2 h01 = __floats2half2_rn(p0, p1);
            const __half2 h23 = __floats2half2_rn(p2, p3);
            QPs[(wm+g)*36 + nf*4 + cc]   = *(const uint32_t*)&h01;
            QPs[(wm+g+8)*36 + nf*4 + cc] = *(const uint32_t*)&h23;
        }
        ls0 += __shfl_xor_sync(0xffffffffu, ls0, 1);
        ls0 += __shfl_xor_sync(0xffffffffu, ls0, 2);
        ls1 += __shfl_xor_sync(0xffffffffu, ls1, 1);
        ls1 += __shfl_xor_sync(0xffffffffu, ls1, 2);
        l0r = l0r * cf0 + ls0;
        l1r = l1r * cf1 + ls1;

#pragma unroll
        for (int nf = 0; nf < 16; nf++) {
            O[nf][0] *= cf0; O[nf][1] *= cf0;
            O[nf][2] *= cf1; O[nf][3] *= cf1;
        }
        __syncthreads();   // P visible

        // ---- O += P @ V : per warp 16x128, 4 k-steps, V via ldmatrix.trans
        const uint32_t vb = VBUF(bf) + vaddrL;
#pragma unroll
        for (int ks = 0; ks < 4; ks++) {
            uint32_t a[4], bb[16][2];
            LDSM_X4(a[0], a[1], a[2], a[3], paddr + ks*32);
#pragma unroll
            for (int nf = 0; nf < 16; nf++)
                LDSM_X2T(bb[nf][0], bb[nf][1], vb + ks*4352 + nf*16);
#pragma unroll
            for (int nf = 0; nf < 16; nf++)
                MMA_F16(O[nf], a, bb[nf]);
        }
        __syncthreads();   // buffers + P fully consumed

        if (t + 2 < 32) LOAD_KV(t + 2, bf);
        CP_WAIT1();        // next tile ready
    }
#undef LOAD_KV

    // epilogue
    const float inv0 = 1.0f / l0r;
    const float inv1 = 1.0f / l1r;
    __half* C0 = CTX + ((size_t)(b*SS + qg0)) * DD + h*DHH;
    __half* C1 = CTX + ((size_t)(b*SS + qg8)) * DD + h*DHH;
#pragma unroll
    for (int nf = 0; nf < 16; nf++) {
        const int c2 = nf*8 + 2*cc;
        const __half2 h0 = __floats2half2_rn(O[nf][0]*inv0, O[nf][1]*inv0);
        const __half2 h1 = __floats2half2_rn(O[nf][2]*inv1, O[nf][3]*inv1);
        *(uint32_t*)(C0 + c2) = *(const uint32_t*)&h0;
        *(uint32_t*)(C1 + c2) = *(const uint32_t*)&h1;
    }
}

// ---------------------------------------------------------------------------
// SwiGLU: f16 in, f16 out
// ---------------------------------------------------------------------------
__global__ void __launch_bounds__(256) swiglu_kernel(
    const __half* __restrict__ AB, __half* __restrict__ G)
{
    const int idx = blockIdx.x * blockDim.x + threadIdx.x;
    const int total4 = ROWS * FFN / 4;
    if (idx >= total4) return;
    const int e = idx * 4;
    const int r = e / FFN;
    const int c = e - r * FFN;
    const __half* row = AB + (size_t)r * NFC;
    __half2 a01 = *(const __half2*)&row[c];
    __half2 a23 = *(const __half2*)&row[c + 2];
    __half2 b01 = *(const __half2*)&row[FFN + c];
    __half2 b23 = *(const __half2*)&row[FFN + c + 2];
    const float a0 = __half2float(a01.x), a1 = __half2float(a01.y);
    const float a2 = __half2float(a23.x), a3 = __half2float(a23.y);
    const float o0 = a0 / (1.0f + __expf(-a0)) * __half2float(b01.x);
    const float o1 = a1 / (1.0f + __expf(-a1)) * __half2float(b01.y);
    const float o2 = a2 / (1.0f + __expf(-a2)) * __half2float(b23.x);
    const float o3 = a3 / (1.0f + __expf(-a3)) * __half2float(b23.y);
    __half2 h0 = __floats2half2_rn(o0, o1);
    __half2 h1 = __floats2half2_rn(o2, o3);
    uint2 pk = { *(const uint32_t*)&h0, *(const uint32_t*)&h1 };
    *(uint2*)&G[(size_t)r * FFN + c] = pk;
}

// ---------------------------------------------------------------------------
// Launch
// ---------------------------------------------------------------------------
extern "C" void kernel_launch(void* const* d_in, const int* in_sizes, int n_in,
                              void* d_out, int out_size)
{
    const float*         hidden  = (const float*)d_in[0];
    const unsigned char* mask    = (const unsigned char*)d_in[1];
    const int*           pos     = (const int*)d_in[2];
    const float*         ln1_g   = (const float*)d_in[3];
    const float*         ln1_b   = (const float*)d_in[4];
    const float*         Wqkv    = (const float*)d_in[5];
    const float*         Wo      = (const float*)d_in[6];
    const float*         ln2_g   = (const float*)d_in[7];
    const float*         ln2_b   = (const float*)d_in[8];
    const float*         Wfc_in  = (const float*)d_in[9];
    const float*         Wfc_out = (const float*)d_in[10];
    float*               out     = (float*)d_out;

    __half *X, *QKV, *Q, *K, *V, *CTX, *X2, *AB, *G;
    __half *WqkvT, *WoT, *WfciT, *WfcoT;
    float *H1;
    cudaGetSymbolAddress((void**)&X,     g_X);
    cudaGetSymbolAddress((void**)&QKV,   g_QKV);
    cudaGetSymbolAddress((void**)&Q,     g_Q);
    cudaGetSymbolAddress((void**)&K,     g_K);
    cudaGetSymbolAddress((void**)&V,     g_V);
    cudaGetSymbolAddress((void**)&CTX,   g_CTX);
    cudaGetSymbolAddress((void**)&H1,    g_H1);
    cudaGetSymbolAddress((void**)&X2,    g_X2);
    cudaGetSymbolAddress((void**)&AB,    g_AB);
    cudaGetSymbolAddress((void**)&G,     g_G);
    cudaGetSymbolAddress((void**)&WqkvT, g_WqkvT);
    cudaGetSymbolAddress((void**)&WoT,   g_WoT);
    cudaGetSymbolAddress((void**)&WfciT, g_WfciT);
    cudaGetSymbolAddress((void**)&WfcoT, g_WfcoT);

    cudaFuncSetAttribute(attn_kernel,
                         cudaFuncAttributeMaxDynamicSharedMemorySize,
                         AT_SMEM_BYTES);
    cudaFuncSetAttribute((tgemm<0,1>),
                         cudaFuncAttributeMaxDynamicSharedMemorySize,
                         GM_SMEM_BYTES);
    cudaFuncSetAttribute((tgemm<1,0>),
                         cudaFuncAttributeMaxDynamicSharedMemorySize,
                         GM_SMEM_BYTES);

    // 0) transpose + fp16 weights -> [N,K]
    transpose_h<<<dim3(NQKV/32, DD/32),  dim3(32,8)>>>(Wqkv,    WqkvT, DD,  NQKV);
    transpose_h<<<dim3(DD/32,   DD/32),  dim3(32,8)>>>(Wo,      WoT,   DD,  DD);
    transpose_h<<<dim3(NFC/32,  DD/32),  dim3(32,8)>>>(Wfc_in,  WfciT, DD,  NFC);
    transpose_h<<<dim3(DD/32,   FFN/32), dim3(32,8)>>>(Wfc_out, WfcoT, FFN, DD);

    // 1) LN1 (fp16 out)
    ln_kernel<<<ROWS, 256>>>(hidden, ln1_g, ln1_b, X);
    // 2) QKV projection (fp16 out)
    tgemm<0,1><<<dim3(NQKV/128, ROWS/128), 256, GM_SMEM_BYTES>>>(
        X, WqkvT, nullptr, QKV, DD, NQKV);
    // 3) RoPE + scatter
    rope_kernel<<<dim3(ROWS, HH), 128>>>(QKV, pos, Q, K, V);
    // 4) attention -> ctx (fp16)
    attn_kernel<<<dim3(SS/128, HH, BB), 256, AT_SMEM_BYTES>>>(Q, K, V, mask, CTX);
    // 5) Wo projection + residual (f32 out)
    tgemm<1,0><<<dim3(DD/128, ROWS/128), 256, GM_SMEM_BYTES>>>(
        CTX, WoT, hidden, H1, DD, DD);
    // 6) LN2 (fp16 out)
    ln_kernel<<<ROWS, 256>>>(H1, ln2_g, ln2_b, X2);
    // 7) fc_in (fp16 out)
    tgemm<0,1><<<dim3(NFC/128, ROWS/128), 256, GM_SMEM_BYTES>>>(
        X2, WfciT, nullptr, AB, DD, NFC);
    // 8) SwiGLU (fp16 out)
    {
        const int total4 = ROWS * FFN / 4;
        swiglu_kernel<<<(total4 + 255)/256, 256>>>(AB, G);
    }
    // 9) fc_out + residual (final output, f32)
    tgemm<1,0><<<dim3(DD/128, ROWS/128), 256, GM_SMEM_BYTES>>>(
        G, WfcoT, H1, out, FFN, DD);
}

// round 8
// speedup vs baseline: 7.1069x; 1.1906x over previous
#include <cuda_runtime.h>
#include <cuda_fp16.h>
#include <math.h>
#include <stdint.h>

// ---------------------------------------------------------------------------
// Problem constants
// ---------------------------------------------------------------------------
#define BB   2
#define SS   2048
#define DD   2048
#define HH   16
#define DHH  128
#define FFN  5632
#define ROWS (BB*SS)           // 4096
#define NQKV (3*HH*DHH)        // 6144
#define NFC  (2*FFN)           // 11264

// ---------------------------------------------------------------------------
// Scratch
// ---------------------------------------------------------------------------
__device__ __half g_X  [ROWS*DD];    // LN1 out
__device__ __half g_QKV[ROWS*NQKV];  // qkv proj (fp16)
__device__ __half g_Q  [ROWS*DD];    // [B,H,S,DH]
__device__ __half g_K  [ROWS*DD];
__device__ __half g_V  [ROWS*DD];    // [B,H,S,DH]
__device__ __half g_CTX[ROWS*DD];    // [B,S,H*DH]
__device__ float  g_H1 [ROWS*DD];    // residual 1 (fp32)
__device__ __half g_X2 [ROWS*DD];    // LN2 out
__device__ __half g_G  [ROWS*FFN];   // swiglu out (written by fused fc_in)
// transposed weights [N,K] K-major, fp16
__device__ __half g_WqkvT [NQKV*DD];
__device__ __half g_WoT   [DD*DD];
__device__ __half g_WfciT [NFC*DD];  // interleaved: row 2j = a_j, 2j+1 = b_j
__device__ __half g_WfcoT [DD*FFN];

// ---------------------------------------------------------------------------
// Helpers
// ---------------------------------------------------------------------------
__device__ __forceinline__ uint32_t smem_u32(const void* p) {
    uint32_t a;
    asm("{ .reg .u64 t; cvta.to.shared.u64 t, %1; cvt.u32.u64 %0, t; }"
        : "=r"(a) : "l"(p));
    return a;
}

#define CP_ASYNC16(dst, src) \
    asm volatile("cp.async.cg.shared.global [%0], [%1], 16;" \
                 :: "r"(dst), "l"(src))
#define CP_COMMIT() asm volatile("cp.async.commit_group;" ::: "memory")
#define CP_WAIT2()  asm volatile("cp.async.wait_group 2;" ::: "memory")
#define CP_WAIT1()  asm volatile("cp.async.wait_group 1;" ::: "memory")
#define CP_WAIT0()  asm volatile("cp.async.wait_group 0;" ::: "memory")

#define MMA_F16(d, a, b)                                                   \
    asm volatile(                                                          \
        "mma.sync.aligned.m16n8k16.row.col.f32.f16.f16.f32 "               \
        "{%0,%1,%2,%3}, {%4,%5,%6,%7}, {%8,%9}, {%0,%1,%2,%3};"            \
        : "+f"((d)[0]), "+f"((d)[1]), "+f"((d)[2]), "+f"((d)[3])           \
        : "r"((a)[0]), "r"((a)[1]), "r"((a)[2]), "r"((a)[3]),              \
          "r"((b)[0]), "r"((b)[1]))

#define LDSM_X4(r0, r1, r2, r3, addr)                                      \
    asm volatile("ldmatrix.sync.aligned.m8n8.x4.shared.b16 "               \
                 "{%0,%1,%2,%3}, [%4];"                                    \
                 : "=r"(r0), "=r"(r1), "=r"(r2), "=r"(r3) : "r"(addr))

#define LDSM_X2(r0, r1, addr)                                              \
    asm volatile("ldmatrix.sync.aligned.m8n8.x2.shared.b16 "               \
                 "{%0,%1}, [%2];"                                          \
                 : "=r"(r0), "=r"(r1) : "r"(addr))

#define LDSM_X2T(r0, r1, addr)                                             \
    asm volatile("ldmatrix.sync.aligned.m8n8.x2.trans.shared.b16 "         \
                 "{%0,%1}, [%2];"                                          \
                 : "=r"(r0), "=r"(r1) : "r"(addr))

// ---------------------------------------------------------------------------
// Weight transpose + fp16 round: W[K,N] f32 -> Wt[N,K] f16
// ---------------------------------------------------------------------------
__global__ void __launch_bounds__(256) transpose_h(
    const float* __restrict__ W, __half* __restrict__ Wt, int K, int N)
{
    __shared__ float t[32][33];
    const int tx = threadIdx.x, ty = threadIdx.y;
    const int n0 = blockIdx.x * 32, k0 = blockIdx.y * 32;
#pragma unroll
    for (int j = 0; j < 4; j++)
        t[ty + j*8][tx] = W[(size_t)(k0 + ty + j*8) * N + n0 + tx];
    __syncthreads();
#pragma unroll
    for (int j = 0; j < 4; j++)
        Wt[(size_t)(n0 + ty + j*8) * K + k0 + tx] = __float2half_rn(t[tx][ty + j*8]);
}

// Paired transpose for fc_in: source col (colOff + j) -> output row (2j + off)
// W: [DD][NFC], Wt: [NFC][DD]
__global__ void __launch_bounds__(256) transpose_h_pair(
    const float* __restrict__ W, __half* __restrict__ Wt,
    int colOff, int rowOff)
{
    __shared__ float t[32][33];
    const int tx = threadIdx.x, ty = threadIdx.y;
    const int n0 = blockIdx.x * 32, k0 = blockIdx.y * 32;
#pragma unroll
    for (int j = 0; j < 4; j++)
        t[ty + j*8][tx] = W[(size_t)(k0 + ty + j*8) * NFC + colOff + n0 + tx];
    __syncthreads();
#pragma unroll
    for (int j = 0; j < 4; j++)
        Wt[(size_t)(2*(n0 + ty + j*8) + rowOff) * DD + k0 + tx] =
            __float2half_rn(t[tx][ty + j*8]);
}

// ---------------------------------------------------------------------------
// FP16 mma.sync GEMM, ldmatrix fragments, 4-stage cp.async pipeline.
// CTA tile 128x128x32, 4 warps (2M x 2N), warp tile 64x64.
// Smem rows: 32 halfs padded to 80 B (granule stride 5 -> conflict-free).
// OUT: 0 = f32 (+residual if EPI), 1 = f16, 2 = f16 fused swiglu (paired cols)
// ---------------------------------------------------------------------------
#define TILE_BYTES 10240              // 128 rows * 80 B
#define STAGE_BYTES (2*TILE_BYTES)
#define GM_SMEM_BYTES (4*STAGE_BYTES) // 81920

template<int EPI, int OUT>
__global__ void __launch_bounds__(128, 2) tgemm(
    const __half* __restrict__ A, const __half* __restrict__ Bt,
    const float* __restrict__ R, void* __restrict__ Cv,
    int K, int N)
{
    extern __shared__ char smc[];
    const uint32_t smb = smem_u32(smc);

    const int tid  = threadIdx.x;
    const int wid  = tid >> 5;
    const int lane = tid & 31;
    const int g    = lane >> 2;
    const int cc   = lane & 3;
    const int wm   = (wid & 1) * 64;
    const int wn   = (wid >> 1) * 64;

    const int m0 = blockIdx.y * 128;
    const int n0 = blockIdx.x * 128;

    const __half* Ab = A  + (size_t)m0 * K;
    const __half* Bb = Bt + (size_t)n0 * K;

    const int NC = K / 32;

    // A frags: lanes 0-15 rows, lanes 16-31 second k-half
    const uint32_t aoff = (uint32_t)(wm + (lane & 15)) * 80 + (lane >> 4) * 16;
    // B frags x4-paired: lanes 0-7 rows n0-7/k0, 8-15 n0-7/k8, 16-23 n8-15/k0,
    // 24-31 n8-15/k8
    const uint32_t boff = (uint32_t)(wn + (lane & 7) + ((lane >> 4) * 8)) * 80
                        + ((lane >> 3) & 1) * 16;

#define LOAD_STAGE(chunk, st) do {                                         \
        const uint32_t asw = smb + (st)*STAGE_BYTES;                       \
        const uint32_t bsw = asw + TILE_BYTES;                             \
        const int kt = (chunk) * 32;                                       \
        _Pragma("unroll")                                                  \
        for (int j = 0; j < 4; j++) {                                      \
            const int f = tid + j * 128;                                   \
            const int row = f >> 2, c4 = f & 3;                            \
            CP_ASYNC16(asw + (uint32_t)(row*80 + c4*16),                   \
                       Ab + (size_t)row * K + kt + c4*8);                  \
            CP_ASYNC16(bsw + (uint32_t)(row*80 + c4*16),                   \
                       Bb + (size_t)row * K + kt + c4*8);                  \
        }                                                                  \
        CP_COMMIT();                                                       \
    } while (0)

    float acc[4][8][4];
#pragma unroll
    for (int mf = 0; mf < 4; mf++)
#pragma unroll
        for (int nf = 0; nf < 8; nf++)
#pragma unroll
            for (int q = 0; q < 4; q++) acc[mf][nf][q] = 0.f;

    LOAD_STAGE(0, 0);
    LOAD_STAGE(1, 1);
    LOAD_STAGE(2, 2);

    for (int i = 0; i < NC; i++) {
        if (i < NC - 2)       CP_WAIT2();
        else if (i == NC - 2) CP_WAIT1();
        else                  CP_WAIT0();
        __syncthreads();
        if (i + 3 < NC) LOAD_STAGE(i + 3, (i + 3) & 3);

        const uint32_t abase = smb + (i & 3) * STAGE_BYTES;
        const uint32_t bbase = abase + TILE_BYTES;

#pragma unroll
        for (int ks = 0; ks < 2; ks++) {
            uint32_t a[4][4], b[8][2];
#pragma unroll
            for (int mf = 0; mf < 4; mf++)
                LDSM_X4(a[mf][0], a[mf][1], a[mf][2], a[mf][3],
                        abase + aoff + mf*1280 + ks*32);
#pragma unroll
            for (int p = 0; p < 4; p++)
                LDSM_X4(b[2*p][0], b[2*p][1], b[2*p+1][0], b[2*p+1][1],
                        bbase + boff + p*1280 + ks*32);
#pragma unroll
            for (int mf = 0; mf < 4; mf++)
#pragma unroll
                for (int nf = 0; nf < 8; nf++)
                    MMA_F16(acc[mf][nf], a[mf], b[nf]);
        }
    }
#undef LOAD_STAGE

#pragma unroll
    for (int mf = 0; mf < 4; mf++) {
#pragma unroll
        for (int nf = 0; nf < 8; nf++) {
            const int row = m0 + wm + mf * 16 + g;
            const int col = n0 + wn + nf * 8 + cc * 2;
            float2 v0 = { acc[mf][nf][0], acc[mf][nf][1] };
            float2 v1 = { acc[mf][nf][2], acc[mf][nf][3] };
            if (OUT == 2) {
                // fused swiglu: even col = a, odd col = b
                __half* Gp = (__half*)Cv;
                const int gcol = col >> 1;
                const float s0 = v0.x / (1.0f + __expf(-v0.x)) * v0.y;
                const float s1 = v1.x / (1.0f + __expf(-v1.x)) * v1.y;
                Gp[(size_t)row * FFN + gcol]       = __float2half_rn(s0);
                Gp[(size_t)(row + 8) * FFN + gcol] = __float2half_rn(s1);
            } else {
                const size_t o0 = (size_t)row * N + col;
                const size_t o1 = (size_t)(row + 8) * N + col;
                if (EPI == 1) {
                    float2 r0 = *(const float2*)&R[o0];
                    float2 r1 = *(const float2*)&R[o1];
                    v0.x += r0.x; v0.y += r0.y;
                    v1.x += r1.x; v1.y += r1.y;
                }
                if (OUT == 1) {
                    __half* C = (__half*)Cv;
                    const __half2 h0 = __floats2half2_rn(v0.x, v0.y);
                    const __half2 h1 = __floats2half2_rn(v1.x, v1.y);
                    *(uint32_t*)&C[o0] = *(const uint32_t*)&h0;
                    *(uint32_t*)&C[o1] = *(const uint32_t*)&h1;
                } else {
                    float* C = (float*)Cv;
                    *(float2*)&C[o0] = v0;
                    *(float2*)&C[o1] = v1;
                }
            }
        }
    }
}

// ---------------------------------------------------------------------------
// LayerNorm: fp32 in, fp16 out
// ---------------------------------------------------------------------------
__global__ void __launch_bounds__(256) ln_kernel(
    const float* __restrict__ X, const float* __restrict__ g,
    const float* __restrict__ b, __half* __restrict__ Y)
{
    const int tid = threadIdx.x;
    const float* x = X + (size_t)blockIdx.x * DD;
    __half* y = Y + (size_t)blockIdx.x * DD;

    float v[8];
    *(float4*)&v[0] = *(const float4*)&x[tid*8];
    *(float4*)&v[4] = *(const float4*)&x[tid*8 + 4];

    float s = 0.f, sq = 0.f;
#pragma unroll
    for (int i = 0; i < 8; i++) { s += v[i]; sq += v[i]*v[i]; }
#pragma unroll
    for (int o = 16; o; o >>= 1) {
        s  += __shfl_xor_sync(0xffffffffu, s,  o);
        sq += __shfl_xor_sync(0xffffffffu, sq, o);
    }
    __shared__ float red[2][8];
    __shared__ float stats[2];
    const int w = tid >> 5, l = tid & 31;
    if (l == 0) { red[0][w] = s; red[1][w] = sq; }
    __syncthreads();
    if (tid == 0) {
        float S = 0.f, SQ = 0.f;
#pragma unroll
        for (int i = 0; i < 8; i++) { S += red[0][i]; SQ += red[1][i]; }
        const float mean = S * (1.0f/DD);
        const float var  = SQ * (1.0f/DD) - mean*mean;
        stats[0] = mean;
        stats[1] = rsqrtf(var + 1e-5f);
    }
    __syncthreads();
    const float mean = stats[0], rstd = stats[1];

    float gv[8], bv[8];
    *(float4*)&gv[0] = *(const float4*)&g[tid*8];
    *(float4*)&gv[4] = *(const float4*)&g[tid*8+4];
    *(float4*)&bv[0] = *(const float4*)&b[tid*8];
    *(float4*)&bv[4] = *(const float4*)&b[tid*8+4];

    __half2 h[4];
#pragma unroll
    for (int i = 0; i < 4; i++) {
        const float a0 = (v[2*i]   - mean) * rstd * gv[2*i]   + bv[2*i];
        const float a1 = (v[2*i+1] - mean) * rstd * gv[2*i+1] + bv[2*i+1];
        h[i] = __floats2half2_rn(a0, a1);
    }
    *(uint4*)&y[tid*8] = *(uint4*)h;
}

// ---------------------------------------------------------------------------
// RoPE + scatter: QKV f16 [B,S,H,3*DH] -> Q/K/V f16 [B,H,S,DH]
// ---------------------------------------------------------------------------
__global__ void __launch_bounds__(128) rope_kernel(
    const __half* __restrict__ QKV, const int* __restrict__ pos_ids,
    __half* __restrict__ Q, __half* __restrict__ K, __half* __restrict__ V)
{
    const int bs = blockIdx.x;
    const int h  = blockIdx.y;
    const int d  = threadIdx.x;
    const int pos = pos_ids[bs];

    const __half* row = QKV + (size_t)bs * NQKV + h * (3*DHH);
    const float q = __half2float(row[d]);
    const float k = __half2float(row[DHH + d]);
    const __half v = row[2*DHH + d];

    const int j = d & 63;
    const float inv = 1.0f / powf(10000.0f, (float)(2*j) * (1.0f/128.0f));
    const float fr = (float)pos * inv;
    const float sn = sinf(fr), cs = cosf(fr);

    float qo, ko;
    if (d < 64) {
        qo = q * cs - __half2float(row[d + 64]) * sn;
        ko = k * cs - __half2float(row[DHH + d + 64]) * sn;
    } else {
        qo = q * cs + __half2float(row[d - 64]) * sn;
        ko = k * cs + __half2float(row[DHH + d - 64]) * sn;
    }
    const int b = bs >> 11, s = bs & 2047;
    const size_t o = (((size_t)(b*HH + h)) * SS + s) * DHH + d;
    Q[o] = __float2half_rn(qo);
    K[o] = __float2half_rn(ko);
    V[o] = v;
}

// ---------------------------------------------------------------------------
// Flash attention (unchanged from R7): fp16 mma + ldmatrix, cp.async
// double-buffered K/V tiles, V via ldmatrix.trans, Q frags in registers.
// ---------------------------------------------------------------------------
#define AT_SMEM_BYTES (26112*4)

__global__ void __launch_bounds__(256) attn_kernel(
    const __half* __restrict__ Q, const __half* __restrict__ K,
    const __half* __restrict__ V, const unsigned char* __restrict__ mask,
    __half* __restrict__ CTX)
{
    extern __shared__ uint32_t smu[];
    uint32_t* QPs = smu;
    const uint32_t smb = smem_u32(smu);
    const uint32_t kB0 = smb + 8704*4;
    const uint32_t vB0 = smb + 17408*4;
#define KBUF(bf) (kB0 + (bf)*17408)
#define VBUF(bf) (vB0 + (bf)*17408)

    const int tid  = threadIdx.x;
    const int lane = tid & 31;
    const int wid  = tid >> 5;
    const int g    = lane >> 2;
    const int cc   = lane & 3;
    const int wm   = wid * 16;

    const int qt = blockIdx.x, h = blockIdx.y, b = blockIdx.z;
    const size_t headoff = ((size_t)(b*HH + h)) * SS * DHH;
    const __half* Qg    = Q + headoff + (size_t)qt * 128 * DHH;
    const __half* Kbase = K + headoff;
    const __half* Vbase = V + headoff;

#pragma unroll
    for (int j = 0; j < 8; j++) {
        const int f = tid + j * 256;
        const int r = f >> 4, c = f & 15;
        CP_ASYNC16(smb + (uint32_t)(r*272 + c*16), Qg + r*DHH + c*8);
    }
    CP_COMMIT();

#define LOAD_KV(t, bf) do {                                                \
        const __half* Kg_ = Kbase + (size_t)(t) * 64 * DHH;                \
        const __half* Vg_ = Vbase + (size_t)(t) * 64 * DHH;                \
        _Pragma("unroll")                                                  \
        for (int j = 0; j < 4; j++) {                                      \
            const int f = tid + j * 256;                                   \
            const int r = f >> 4, c = f & 15;                              \
            CP_ASYNC16(KBUF(bf) + (uint32_t)(r*272 + c*16),                \
                       Kg_ + r*DHH + c*8);                                 \
            CP_ASYNC16(VBUF(bf) + (uint32_t)(r*272 + c*16),                \
                       Vg_ + r*DHH + c*8);                                 \
        }                                                                  \
        CP_COMMIT();                                                       \
    } while (0)

    LOAD_KV(0, 0);
    LOAD_KV(1, 1);

    CP_WAIT1();
    __syncthreads();

    uint32_t qf[8][4];
    {
        const uint32_t qaddr = smb + (uint32_t)(wm + (lane & 15)) * 272
                             + (lane >> 4) * 16;
#pragma unroll
        for (int ks = 0; ks < 8; ks++)
            LDSM_X4(qf[ks][0], qf[ks][1], qf[ks][2], qf[ks][3], qaddr + ks*32);
    }
    __syncthreads();

    const uint32_t kaddrL = (uint32_t)(lane & 7) * 272 + ((lane >> 3) & 1) * 16;
    const uint32_t vaddrL = (uint32_t)(lane & 15) * 272;
    const uint32_t paddr  = smb + (uint32_t)(wm + (lane & 15)) * 144
                          + (lane >> 4) * 16;

    float m0r = -1e30f, m1r = -1e30f, l0r = 0.f, l1r = 0.f;
    float O[16][4];
#pragma unroll
    for (int nf = 0; nf < 16; nf++)
#pragma unroll
        for (int q = 0; q < 4; q++) O[nf][q] = 0.f;

    const float scale = 0.08838834764831845f;
    const unsigned char* mrow = mask + (size_t)b * SS * SS;
    const int qg0 = qt * 128 + wm + g;
    const int qg8 = qg0 + 8;

    for (int t = 0; t < 32; t++) {
        const int bf = t & 1;
        const int kt = t * 64;

        unsigned short mRa[8], mRb[8];
        {
            const unsigned char* mpA = mrow + (size_t)qg0 * SS + kt + 2*cc;
            const unsigned char* mpB = mrow + (size_t)qg8 * SS + kt + 2*cc;
#pragma unroll
            for (int nf = 0; nf < 8; nf++) {
                mRa[nf] = *(const unsigned short*)(mpA + nf*8);
                mRb[nf] = *(const unsigned short*)(mpB + nf*8);
            }
        }

        float s[8][4];
#pragma unroll
        for (int nf = 0; nf < 8; nf++)
#pragma unroll
            for (int q = 0; q < 4; q++) s[nf][q] = 0.f;

        const uint32_t kb = KBUF(bf) + kaddrL;
#pragma unroll
        for (int ks = 0; ks < 8; ks++) {
            uint32_t bb[8][2];
#pragma unroll
            for (int nf = 0; nf < 8; nf++)
                LDSM_X2(bb[nf][0], bb[nf][1], kb + nf*2176 + ks*32);
#pragma unroll
            for (int nf = 0; nf < 8; nf++)
                MMA_F16(s[nf], qf[ks], bb[nf]);
        }

        float rmax0 = -1e30f, rmax1 = -1e30f;
#pragma unroll
        for (int nf = 0; nf < 8; nf++) {
            float s0 = s[nf][0]*scale, s1 = s[nf][1]*scale;
            float s2 = s[nf][2]*scale, s3 = s[nf][3]*scale;
            if (mRa[nf] & 0x00ffu) s0 = -10000.f;
            if (mRa[nf] & 0xff00u) s1 = -10000.f;
            if (mRb[nf] & 0x00ffu) s2 = -10000.f;
            if (mRb[nf] & 0xff00u) s3 = -10000.f;
            s[nf][0] = s0; s[nf][1] = s1; s[nf][2] = s2; s[nf][3] = s3;
            rmax0 = fmaxf(rmax0, fmaxf(s0, s1));
            rmax1 = fmaxf(rmax1, fmaxf(s2, s3));
        }
        rmax0 = fmaxf(rmax0, __shfl_xor_sync(0xffffffffu, rmax0, 1));
        rmax0 = fmaxf(rmax0, __shfl_xor_sync(0xffffffffu, rmax0, 2));
        rmax1 = fmaxf(rmax1, __shfl_xor_sync(0xffffffffu, rmax1, 1));
        rmax1 = fmaxf(rmax1, __shfl_xor_sync(0xffffffffu, rmax1, 2));

        const float mn0 = fmaxf(m0r, rmax0);
        const float mn1 = fmaxf(m1r, rmax1);
        const float cf0 = __expf(m0r - mn0);
        const float cf1 = __expf(m1r - mn1);
        m0r = mn0; m1r = mn1;

        float ls0 = 0.f, ls1 = 0.f;
#pragma unroll
        for (int nf = 0; nf < 8; nf++) {
            const float p0 = __expf(s[nf][0] - mn0);
            const float p1 = __expf(s[nf][1] - mn0);
            const float p2 = __expf(s[nf][2] - mn1);
            const float p3 = __expf(s[nf][3] - mn1);
            ls0 += p0 + p1; ls1 += p2 + p3;
            const __half2 h01 = __floats2half2_rn(p0, p1);
            const __half2 h23 = __floats2half2_rn(p2, p3);
            QPs[(wm+g)*36 + nf*4 + cc]   = *(const uint32_t*)&h01;
            QPs[(wm+g+8)*36 + nf*4 + cc] = *(const uint32_t*)&h23;
        }
        ls0 += __shfl_xor_sync(0xffffffffu, ls0, 1);
        ls0 += __shfl_xor_sync(0xffffffffu, ls0, 2);
        ls1 += __shfl_xor_sync(0xffffffffu, ls1, 1);
        ls1 += __shfl_xor_sync(0xffffffffu, ls1, 2);
        l0r = l0r * cf0 + ls0;
        l1r = l1r * cf1 + ls1;

#pragma unroll
        for (int nf = 0; nf < 16; nf++) {
            O[nf][0] *= cf0; O[nf][1] *= cf0;
            O[nf][2] *= cf1; O[nf][3] *= cf1;
        }
        __syncthreads();

        const uint32_t vb = VBUF(bf) + vaddrL;
#pragma unroll
        for (int ks = 0; ks < 4; ks++) {
            uint32_t a[4], bb[16][2];
            LDSM_X4(a[0], a[1], a[2], a[3], paddr + ks*32);
#pragma unroll
            for (int nf = 0; nf < 16; nf++)
                LDSM_X2T(bb[nf][0], bb[nf][1], vb + ks*4352 + nf*16);
#pragma unroll
            for (int nf = 0; nf < 16; nf++)
                MMA_F16(O[nf], a, bb[nf]);
        }
        __syncthreads();

        if (t + 2 < 32) LOAD_KV(t + 2, bf);
        CP_WAIT1();
    }
#undef LOAD_KV

    const float inv0 = 1.0f / l0r;
    const float inv1 = 1.0f / l1r;
    __half* C0 = CTX + ((size_t)(b*SS + qg0)) * DD + h*DHH;
    __half* C1 = CTX + ((size_t)(b*SS + qg8)) * DD + h*DHH;
#pragma unroll
    for (int nf = 0; nf < 16; nf++) {
        const int c2 = nf*8 + 2*cc;
        const __half2 h0 = __floats2half2_rn(O[nf][0]*inv0, O[nf][1]*inv0);
        const __half2 h1 = __floats2half2_rn(O[nf][2]*inv1, O[nf][3]*inv1);
        *(uint32_t*)(C0 + c2) = *(const uint32_t*)&h0;
        *(uint32_t*)(C1 + c2) = *(const uint32_t*)&h1;
    }
}

// ---------------------------------------------------------------------------
// Launch
// ---------------------------------------------------------------------------
extern "C" void kernel_launch(void* const* d_in, const int* in_sizes, int n_in,
                              void* d_out, int out_size)
{
    const float*         hidden  = (const float*)d_in[0];
    const unsigned char* mask    = (const unsigned char*)d_in[1];
    const int*           pos     = (const int*)d_in[2];
    const float*         ln1_g   = (const float*)d_in[3];
    const float*         ln1_b   = (const float*)d_in[4];
    const float*         Wqkv    = (const float*)d_in[5];
    const float*         Wo      = (const float*)d_in[6];
    const float*         ln2_g   = (const float*)d_in[7];
    const float*         ln2_b   = (const float*)d_in[8];
    const float*         Wfc_in  = (const float*)d_in[9];
    const float*         Wfc_out = (const float*)d_in[10];
    float*               out     = (float*)d_out;

    __half *X, *QKV, *Q, *K, *V, *CTX, *X2, *G;
    __half *WqkvT, *WoT, *WfciT, *WfcoT;
    float *H1;
    cudaGetSymbolAddress((void**)&X,     g_X);
    cudaGetSymbolAddress((void**)&QKV,   g_QKV);
    cudaGetSymbolAddress((void**)&Q,     g_Q);
    cudaGetSymbolAddress((void**)&K,     g_K);
    cudaGetSymbolAddress((void**)&V,     g_V);
    cudaGetSymbolAddress((void**)&CTX,   g_CTX);
    cudaGetSymbolAddress((void**)&H1,    g_H1);
    cudaGetSymbolAddress((void**)&X2,    g_X2);
    cudaGetSymbolAddress((void**)&G,     g_G);
    cudaGetSymbolAddress((void**)&WqkvT, g_WqkvT);
    cudaGetSymbolAddress((void**)&WoT,   g_WoT);
    cudaGetSymbolAddress((void**)&WfciT, g_WfciT);
    cudaGetSymbolAddress((void**)&WfcoT, g_WfcoT);

    cudaFuncSetAttribute(attn_kernel,
                         cudaFuncAttributeMaxDynamicSharedMemorySize,
                         AT_SMEM_BYTES);
    cudaFuncSetAttribute((tgemm<0,1>),
                         cudaFuncAttributeMaxDynamicSharedMemorySize,
                         GM_SMEM_BYTES);
    cudaFuncSetAttribute((tgemm<1,0>),
                         cudaFuncAttributeMaxDynamicSharedMemorySize,
                         GM_SMEM_BYTES);
    cudaFuncSetAttribute((tgemm<0,2>),
                         cudaFuncAttributeMaxDynamicSharedMemorySize,
                         GM_SMEM_BYTES);

    // 0) transpose + fp16 weights -> [N,K]
    transpose_h<<<dim3(NQKV/32, DD/32),  dim3(32,8)>>>(Wqkv,    WqkvT, DD,  NQKV);
    transpose_h<<<dim3(DD/32,   DD/32),  dim3(32,8)>>>(Wo,      WoT,   DD,  DD);
    transpose_h<<<dim3(DD/32,   FFN/32), dim3(32,8)>>>(Wfc_out, WfcoT, FFN, DD);
    // fc_in: interleaved rows (2j = a_j, 2j+1 = b_j)
    transpose_h_pair<<<dim3(FFN/32, DD/32), dim3(32,8)>>>(Wfc_in, WfciT, 0,   0);
    transpose_h_pair<<<dim3(FFN/32, DD/32), dim3(32,8)>>>(Wfc_in, WfciT, FFN, 1);

    // 1) LN1 (fp16 out)
    ln_kernel<<<ROWS, 256>>>(hidden, ln1_g, ln1_b, X);
    // 2) QKV projection (fp16 out)
    tgemm<0,1><<<dim3(NQKV/128, ROWS/128), 128, GM_SMEM_BYTES>>>(
        X, WqkvT, nullptr, QKV, DD, NQKV);
    // 3) RoPE + scatter
    rope_kernel<<<dim3(ROWS, HH), 128>>>(QKV, pos, Q, K, V);
    // 4) attention -> ctx (fp16)
    attn_kernel<<<dim3(SS/128, HH, BB), 256, AT_SMEM_BYTES>>>(Q, K, V, mask, CTX);
    // 5) Wo projection + residual (f32 out)
    tgemm<1,0><<<dim3(DD/128, ROWS/128), 128, GM_SMEM_BYTES>>>(
        CTX, WoT, hidden, H1, DD, DD);
    // 6) LN2 (fp16 out)
    ln_kernel<<<ROWS, 256>>>(H1, ln2_g, ln2_b, X2);
    // 7) fc_in + fused SwiGLU (fp16 G out)
    tgemm<0,2><<<dim3(NFC/128, ROWS/128), 128, GM_SMEM_BYTES>>>(
        X2, WfciT, nullptr, G, DD, NFC);
    // 8) fc_out + residual (final output, f32)
    tgemm<1,0><<<dim3(DD/128, ROWS/128), 128, GM_SMEM_BYTES>>>(
        G, WfcoT, H1, out, FFN, DD);
}